// round 1
// baseline (speedup 1.0000x reference)
#include <cuda_runtime.h>
#include <math.h>

#define N_TOK   2048
#define D_MODEL 2048
#define KV_D    512
#define HD      128

// Scratch (static device globals: allocation-guard safe)
__device__ float g_Q[N_TOK * D_MODEL];
__device__ float g_K[N_TOK * KV_D];
__device__ float g_V[N_TOK * KV_D];
__device__ float g_ctx[N_TOK * D_MODEL];

// ---------------------------------------------------------------------------
// SGEMM: C[M,N] = A[M,K] @ B[K,N], row-major, fp32. 128x128x8 tile, 8x8 micro.
// Requires M,N % 128 == 0, K % 8 == 0, all pointers 16B aligned.
// ---------------------------------------------------------------------------
__global__ void __launch_bounds__(256) sgemm_kernel(const float* __restrict__ A,
                                                    const float* __restrict__ B,
                                                    float* __restrict__ C,
                                                    int M, int N, int K) {
    __shared__ float As[8][128];
    __shared__ float Bs[8][128];
    const int tid  = threadIdx.x;
    const int tr   = tid >> 4;        // 0..15
    const int tc   = tid & 15;        // 0..15
    const int arow = tid >> 1;        // 0..127
    const int acol = (tid & 1) * 4;   // 0 or 4
    const int brow = tid >> 5;        // 0..7
    const int bcol = (tid & 31) * 4;  // 0..124

    const float* Ab = A + (size_t)blockIdx.y * 128 * K;
    const float* Bb = B + blockIdx.x * 128;

    float acc[8][8];
#pragma unroll
    for (int i = 0; i < 8; ++i)
#pragma unroll
        for (int j = 0; j < 8; ++j) acc[i][j] = 0.f;

    for (int k0 = 0; k0 < K; k0 += 8) {
        float4 av = *(const float4*)(Ab + (size_t)arow * K + k0 + acol);
        As[acol + 0][arow] = av.x;
        As[acol + 1][arow] = av.y;
        As[acol + 2][arow] = av.z;
        As[acol + 3][arow] = av.w;
        *(float4*)(&Bs[brow][bcol]) =
            *(const float4*)(B + (size_t)(k0 + brow) * N + blockIdx.x * 128 + bcol);
        __syncthreads();
#pragma unroll
        for (int k = 0; k < 8; ++k) {
            float ra[8], rb[8];
            *(float4*)(ra)     = *(const float4*)(&As[k][tr * 8]);
            *(float4*)(ra + 4) = *(const float4*)(&As[k][tr * 8 + 4]);
            *(float4*)(rb)     = *(const float4*)(&Bs[k][tc * 8]);
            *(float4*)(rb + 4) = *(const float4*)(&Bs[k][tc * 8 + 4]);
#pragma unroll
            for (int i = 0; i < 8; ++i)
#pragma unroll
                for (int j = 0; j < 8; ++j)
                    acc[i][j] = fmaf(ra[i], rb[j], acc[i][j]);
        }
        __syncthreads();
    }
#pragma unroll
    for (int i = 0; i < 8; ++i) {
        float* Crow = C + (size_t)(blockIdx.y * 128 + tr * 8 + i) * N + blockIdx.x * 128 + tc * 8;
        *(float4*)(Crow)     = make_float4(acc[i][0], acc[i][1], acc[i][2], acc[i][3]);
        *(float4*)(Crow + 4) = make_float4(acc[i][4], acc[i][5], acc[i][6], acc[i][7]);
    }
    (void)M; (void)Bb;
}

// ---------------------------------------------------------------------------
// RoPE in-place on buf[rows][cols], interleaved pairs within each 128-col head
// block. pair i (of 64): angle = t * theta^{-i/64}. fp64 angle for accuracy.
// ---------------------------------------------------------------------------
__global__ void rope_kernel(float* __restrict__ buf, int rows, int cols) {
    int p = blockIdx.x * blockDim.x + threadIdx.x;
    int half = cols >> 1;
    int total = rows * half;
    if (p >= total) return;
    int t   = p / half;
    int pr  = p - t * half;
    int i   = pr & 63;
    int blk = pr >> 6;
    // inv_freq = 10000^{-(2i)/128} = exp(-ln(10000) * i/64)
    double inv = exp(-9.210340371976184 * ((double)i / 64.0));
    double ang = (double)t * inv;
    double sd, cd;
    sincos(ang, &sd, &cd);
    float cf = (float)cd, sf = (float)sd;
    float* pb = buf + (size_t)t * cols + blk * 128 + 2 * i;
    float xe = pb[0], xo = pb[1];
    pb[0] = xe * cf - xo * sf;
    pb[1] = xe * sf + xo * cf;
}

// ---------------------------------------------------------------------------
// Flash attention, causal, fp32. One block = 64 query rows x one q-head.
// grid (32 qtiles, 16 heads), 256 threads.
// Q layout: cols g*512 + kv*128 + d ; K/V: kv*128 + d ; ctx: (kv*4+g)*128 + d.
// ---------------------------------------------------------------------------
__global__ void __launch_bounds__(256) flash_kernel(const float* __restrict__ Q,
                                                    const float* __restrict__ Kb,
                                                    const float* __restrict__ Vb,
                                                    float* __restrict__ ctx) {
    const int qt = blockIdx.x;       // 0..31
    const int h  = blockIdx.y;       // 0..15
    const int g  = h >> 2, kv = h & 3;
    const int qcol0 = g * 512 + kv * 128;
    const int kcol0 = kv * 128;
    const int ocol0 = (kv * 4 + g) * 128;

    extern __shared__ float sm[];
    float* Qt       = sm;               // [128][64] (transposed)
    float* Kt       = Qt + 128 * 64;    // [128][64] (transposed)
    float* Vs       = Kt + 128 * 64;    // [64][128]
    float* S        = Vs + 64 * 128;    // [64][65]  (padded)
    float* rowM     = S + 64 * 65;
    float* rowL     = rowM + 64;
    float* rowScale = rowL + 64;

    const int tid = threadIdx.x;
    const int tr  = tid >> 4, tc = tid & 15;
    const int i0  = tr * 4;
    const float SCALE = 0.08838834764831845f;  // 1/sqrt(128)

    // Load Q tile, transposed
#pragma unroll
    for (int it = 0; it < 8; ++it) {
        int e = (it * 256 + tid) * 4;
        int r = e >> 7, c = e & 127;
        float4 v = *(const float4*)(Q + (size_t)(qt * 64 + r) * 2048 + qcol0 + c);
        Qt[(c + 0) * 64 + r] = v.x;
        Qt[(c + 1) * 64 + r] = v.y;
        Qt[(c + 2) * 64 + r] = v.z;
        Qt[(c + 3) * 64 + r] = v.w;
    }
    if (tid < 64) { rowM[tid] = -INFINITY; rowL[tid] = 0.f; }

    float acc[4][8];
#pragma unroll
    for (int r = 0; r < 4; ++r)
#pragma unroll
        for (int c = 0; c < 8; ++c) acc[r][c] = 0.f;

    for (int kt = 0; kt <= qt; ++kt) {
        __syncthreads();  // prior iter done reading Kt/Vs/S; Qt stores visible
        // Load K (transposed) and V tiles
#pragma unroll
        for (int it = 0; it < 8; ++it) {
            int e = (it * 256 + tid) * 4;
            int r = e >> 7, c = e & 127;
            float4 kvv = *(const float4*)(Kb + (size_t)(kt * 64 + r) * 512 + kcol0 + c);
            Kt[(c + 0) * 64 + r] = kvv.x;
            Kt[(c + 1) * 64 + r] = kvv.y;
            Kt[(c + 2) * 64 + r] = kvv.z;
            Kt[(c + 3) * 64 + r] = kvv.w;
            *(float4*)(Vs + r * 128 + c) =
                *(const float4*)(Vb + (size_t)(kt * 64 + r) * 512 + kcol0 + c);
        }
        __syncthreads();

        // S[64][64] = Q K^T (micro 4x4 per thread)
        float sacc[4][4];
#pragma unroll
        for (int i = 0; i < 4; ++i)
#pragma unroll
            for (int j = 0; j < 4; ++j) sacc[i][j] = 0.f;
#pragma unroll 4
        for (int dd = 0; dd < 128; ++dd) {
            float4 a = *(const float4*)(Qt + dd * 64 + i0);
            float4 b = *(const float4*)(Kt + dd * 64 + tc * 4);
            float ra[4] = {a.x, a.y, a.z, a.w};
            float rb[4] = {b.x, b.y, b.z, b.w};
#pragma unroll
            for (int i = 0; i < 4; ++i)
#pragma unroll
                for (int j = 0; j < 4; ++j)
                    sacc[i][j] = fmaf(ra[i], rb[j], sacc[i][j]);
        }
        // scale + causal mask, write to smem
#pragma unroll
        for (int i = 0; i < 4; ++i)
#pragma unroll
            for (int j = 0; j < 4; ++j) {
                float sv = sacc[i][j] * SCALE;
                if (kt == qt && (tc * 4 + j) > (i0 + i)) sv = -INFINITY;
                S[(i0 + i) * 65 + tc * 4 + j] = sv;
            }
        __syncthreads();

        // Online softmax row pass (64 threads, one row each)
        if (tid < 64) {
            float mo = rowM[tid];
            float mx = mo;
#pragma unroll 8
            for (int j = 0; j < 64; ++j) mx = fmaxf(mx, S[tid * 65 + j]);
            float sc = expf(mo - mx);  // mo=-inf first tile -> 0
            float sum = 0.f;
#pragma unroll 8
            for (int j = 0; j < 64; ++j) {
                float pv = expf(S[tid * 65 + j] - mx);
                S[tid * 65 + j] = pv;
                sum += pv;
            }
            rowL[tid]     = rowL[tid] * sc + sum;
            rowM[tid]     = mx;
            rowScale[tid] = sc;
        }
        __syncthreads();

        // O = O*scale + P @ V   (thread: 4 rows x 8 cols)
#pragma unroll
        for (int r = 0; r < 4; ++r) {
            float sc = rowScale[i0 + r];
#pragma unroll
            for (int c = 0; c < 8; ++c) acc[r][c] *= sc;
        }
#pragma unroll 2
        for (int j = 0; j < 64; ++j) {
            float p0 = S[(i0 + 0) * 65 + j];
            float p1 = S[(i0 + 1) * 65 + j];
            float p2 = S[(i0 + 2) * 65 + j];
            float p3 = S[(i0 + 3) * 65 + j];
            float4 v0 = *(const float4*)(Vs + j * 128 + tc * 8);
            float4 v1 = *(const float4*)(Vs + j * 128 + tc * 8 + 4);
            float vv[8] = {v0.x, v0.y, v0.z, v0.w, v1.x, v1.y, v1.z, v1.w};
#pragma unroll
            for (int c = 0; c < 8; ++c) {
                acc[0][c] = fmaf(p0, vv[c], acc[0][c]);
                acc[1][c] = fmaf(p1, vv[c], acc[1][c]);
                acc[2][c] = fmaf(p2, vv[c], acc[2][c]);
                acc[3][c] = fmaf(p3, vv[c], acc[3][c]);
            }
        }
    }

    // Normalize and write ctx
#pragma unroll
    for (int r = 0; r < 4; ++r) {
        float inv = 1.f / rowL[i0 + r];
        float* dst = ctx + (size_t)(qt * 64 + i0 + r) * 2048 + ocol0 + tc * 8;
        *(float4*)(dst)     = make_float4(acc[r][0] * inv, acc[r][1] * inv,
                                          acc[r][2] * inv, acc[r][3] * inv);
        *(float4*)(dst + 4) = make_float4(acc[r][4] * inv, acc[r][5] * inv,
                                          acc[r][6] * inv, acc[r][7] * inv);
    }
}

// ---------------------------------------------------------------------------
extern "C" void kernel_launch(void* const* d_in, const int* in_sizes, int n_in,
                              void* d_out, int out_size) {
    const float* x  = (const float*)d_in[0];
    const float* Wq = (const float*)d_in[1];
    const float* Wk = (const float*)d_in[2];
    const float* Wv = (const float*)d_in[3];
    const float* Wo = (const float*)d_in[4];
    float* out = (float*)d_out;

    float *Qb, *Kb, *Vb, *Cb;
    cudaGetSymbolAddress((void**)&Qb, g_Q);
    cudaGetSymbolAddress((void**)&Kb, g_K);
    cudaGetSymbolAddress((void**)&Vb, g_V);
    cudaGetSymbolAddress((void**)&Cb, g_ctx);

    dim3 blk(256);
    // Projections
    sgemm_kernel<<<dim3(D_MODEL / 128, N_TOK / 128), blk>>>(x, Wq, Qb, N_TOK, D_MODEL, D_MODEL);
    sgemm_kernel<<<dim3(KV_D / 128, N_TOK / 128), blk>>>(x, Wk, Kb, N_TOK, KV_D, D_MODEL);
    sgemm_kernel<<<dim3(KV_D / 128, N_TOK / 128), blk>>>(x, Wv, Vb, N_TOK, KV_D, D_MODEL);
    // RoPE on Q and K
    rope_kernel<<<(N_TOK * (D_MODEL / 2) + 255) / 256, 256>>>(Qb, N_TOK, D_MODEL);
    rope_kernel<<<(N_TOK * (KV_D / 2) + 255) / 256, 256>>>(Kb, N_TOK, KV_D);
    // Flash attention
    size_t smem = (size_t)(128 * 64 * 2 + 64 * 128 + 64 * 65 + 192) * sizeof(float);
    cudaFuncSetAttribute(flash_kernel, cudaFuncAttributeMaxDynamicSharedMemorySize, (int)smem);
    flash_kernel<<<dim3(N_TOK / 64, 16), blk, smem>>>(Qb, Kb, Vb, Cb);
    // Output projection
    sgemm_kernel<<<dim3(D_MODEL / 128, N_TOK / 128), blk>>>(Cb, Wo, out, N_TOK, D_MODEL, D_MODEL);

    (void)in_sizes; (void)n_in; (void)out_size;
}

// round 3
// speedup vs baseline: 1.8403x; 1.8403x over previous
#include <cuda_runtime.h>
#include <cuda_bf16.h>
#include <math.h>
#include <stdint.h>

#define N_TOK   2048
#define D_MODEL 2048
#define KV_D    512

// ---------------- scratch (device globals: allocation-guard safe) ----------
__device__ float g_Q[N_TOK * D_MODEL];
__device__ float g_K[N_TOK * KV_D];
__device__ float g_V[N_TOK * KV_D];
__device__ float g_ctx[N_TOK * D_MODEL];

__device__ __nv_bfloat16 g_xh[N_TOK * D_MODEL];
__device__ __nv_bfloat16 g_xl[N_TOK * D_MODEL];
__device__ __nv_bfloat16 g_ch[N_TOK * D_MODEL];
__device__ __nv_bfloat16 g_cl[N_TOK * D_MODEL];
__device__ __nv_bfloat16 g_WqTh[D_MODEL * D_MODEL];
__device__ __nv_bfloat16 g_WqTl[D_MODEL * D_MODEL];
__device__ __nv_bfloat16 g_WkTh[KV_D * D_MODEL];
__device__ __nv_bfloat16 g_WkTl[KV_D * D_MODEL];
__device__ __nv_bfloat16 g_WvTh[KV_D * D_MODEL];
__device__ __nv_bfloat16 g_WvTl[KV_D * D_MODEL];
__device__ __nv_bfloat16 g_WoTh[D_MODEL * D_MODEL];
__device__ __nv_bfloat16 g_WoTl[D_MODEL * D_MODEL];

__device__ __forceinline__ uint32_t smem_u32(const void* p) {
    uint32_t a;
    asm("{ .reg .u64 t; cvta.to.shared.u64 t, %1; cvt.u32.u64 %0, t; }"
        : "=r"(a) : "l"(p));
    return a;
}

#define LDSM4(r, addr)                                                        \
    asm volatile("ldmatrix.sync.aligned.m8n8.x4.shared.b16 {%0,%1,%2,%3}, [%4];" \
                 : "=r"((r)[0]), "=r"((r)[1]), "=r"((r)[2]), "=r"((r)[3])     \
                 : "r"(addr))

#define MMA16816(d, a, b0, b1)                                                \
    asm volatile("mma.sync.aligned.m16n8k16.row.col.f32.bf16.bf16.f32 "       \
                 "{%0,%1,%2,%3}, {%4,%5,%6,%7}, {%8,%9}, {%0,%1,%2,%3};"      \
                 : "+f"((d)[0]), "+f"((d)[1]), "+f"((d)[2]), "+f"((d)[3])     \
                 : "r"((a)[0]), "r"((a)[1]), "r"((a)[2]), "r"((a)[3]),        \
                   "r"(b0), "r"(b1))

// ---------------------------------------------------------------------------
// Split/convert kernels
// ---------------------------------------------------------------------------
__global__ void conv_act(const float* __restrict__ in,
                         __nv_bfloat16* __restrict__ oh,
                         __nv_bfloat16* __restrict__ ol, int n) {
    int i = (blockIdx.x * blockDim.x + threadIdx.x) * 4;
    if (i >= n) return;
    float4 v = *(const float4*)(in + i);
    __nv_bfloat16 h0 = __float2bfloat16(v.x);
    __nv_bfloat16 h1 = __float2bfloat16(v.y);
    __nv_bfloat16 h2 = __float2bfloat16(v.z);
    __nv_bfloat16 h3 = __float2bfloat16(v.w);
    __nv_bfloat16 l0 = __float2bfloat16(v.x - __bfloat162float(h0));
    __nv_bfloat16 l1 = __float2bfloat16(v.y - __bfloat162float(h1));
    __nv_bfloat16 l2 = __float2bfloat16(v.z - __bfloat162float(h2));
    __nv_bfloat16 l3 = __float2bfloat16(v.w - __bfloat162float(h3));
    __nv_bfloat162* ph = (__nv_bfloat162*)(oh + i);
    __nv_bfloat162* pl = (__nv_bfloat162*)(ol + i);
    ph[0] = __nv_bfloat162(h0, h1); ph[1] = __nv_bfloat162(h2, h3);
    pl[0] = __nv_bfloat162(l0, l1); pl[1] = __nv_bfloat162(l2, l3);
}

// W [Kdim, Ndim] row-major fp32 -> WT [Ndim, Kdim] hi/lo bf16
__global__ void conv_wT(const float* __restrict__ in,
                        __nv_bfloat16* __restrict__ oh,
                        __nv_bfloat16* __restrict__ ol, int Kdim, int Ndim) {
    __shared__ float t[32][33];
    int n0 = blockIdx.x * 32, k0 = blockIdx.y * 32;
    int tx = threadIdx.x, ty = threadIdx.y;
#pragma unroll
    for (int i = 0; i < 4; ++i)
        t[ty + 8 * i][tx] = in[(size_t)(k0 + ty + 8 * i) * Ndim + n0 + tx];
    __syncthreads();
#pragma unroll
    for (int i = 0; i < 4; ++i) {
        int nl = ty + 8 * i;
        float v = t[tx][nl];
        __nv_bfloat16 h = __float2bfloat16(v);
        __nv_bfloat16 l = __float2bfloat16(v - __bfloat162float(h));
        size_t o = (size_t)(n0 + nl) * Kdim + k0 + tx;
        oh[o] = h; ol[o] = l;
    }
}

// ---------------------------------------------------------------------------
// bf16x3-split HGEMM (mma.sync): C[M,N] = A[M,K] @ Bt[N,K]^T, fp32 out.
// BM=128, BK=32, BN template (128 or 64). 256 threads, warp grid 4(m) x 2(n).
// Smem rows padded to 80B -> conflict-free ldmatrix.
// ---------------------------------------------------------------------------
template <int BN>
__global__ void __launch_bounds__(256) hgemm3(
    const __nv_bfloat16* __restrict__ Ah, const __nv_bfloat16* __restrict__ Al,
    const __nv_bfloat16* __restrict__ Bh, const __nv_bfloat16* __restrict__ Bl,
    float* __restrict__ C, int N, int K) {
    constexpr int BM = 128;
    constexpr int WN = BN / 2;        // per-warp n extent
    constexpr int NBF = WN / 16;      // B ldmatrix.x4 count per split
    constexpr int NJ = WN / 8;        // n8 tiles per warp
    constexpr int RS = 80;            // smem row stride (bytes)
    constexpr int OAl = BM * RS;
    constexpr int OBh = 2 * BM * RS;
    constexpr int OBl = 2 * BM * RS + BN * RS;
    constexpr int SBUF = 2 * BM * RS + 2 * BN * RS;
    constexpr int NBCH = BN * 4 / 256;  // B 16B-chunks per thread

    extern __shared__ char smem[];
    const uint32_t sbase = smem_u32(smem);

    const int tid = threadIdx.x;
    const int lane = tid & 31;
    const int wid = tid >> 5;
    const int warp_m = wid & 3;
    const int warp_n = wid >> 2;

    const int m0 = blockIdx.y * BM;
    const int n0 = blockIdx.x * BN;
    const __nv_bfloat16* pAh = Ah + (size_t)m0 * K;
    const __nv_bfloat16* pAl = Al + (size_t)m0 * K;
    const __nv_bfloat16* pBh = Bh + (size_t)n0 * K;
    const __nv_bfloat16* pBl = Bl + (size_t)n0 * K;

    // ldmatrix per-lane address components
    const int q = lane >> 3;
    const int rowA = (lane & 7) + (q & 1) * 8;          // A: q order (m0k0)(m8k0)(m0k8)(m8k8)
    const int colA = (q >> 1) * 16;
    const int rowB = (lane & 7) + (q >> 1) * 8;         // B: q order (n0k0)(n0k8)(n8k0)(n8k8)
    const int colB = (q & 1) * 16;

    float acc[2][NJ][4];
#pragma unroll
    for (int im = 0; im < 2; ++im)
#pragma unroll
        for (int j = 0; j < NJ; ++j)
#pragma unroll
            for (int e = 0; e < 4; ++e) acc[im][j][e] = 0.f;

    const int NC = K / 32;

    // ---- prologue: chunk 0 -> buffer 0
    {
        char* db = smem;
#pragma unroll
        for (int i = 0; i < 2; ++i) {
            int idx = tid + i * 256;
            int r = idx >> 2, c = idx & 3;
            *(uint4*)(db + r * RS + c * 16) =
                *(const uint4*)((const char*)pAh + ((size_t)r * K) * 2 + c * 16);
            *(uint4*)(db + OAl + r * RS + c * 16) =
                *(const uint4*)((const char*)pAl + ((size_t)r * K) * 2 + c * 16);
        }
#pragma unroll
        for (int i = 0; i < NBCH; ++i) {
            int idx = tid + i * 256;
            int r = idx >> 2, c = idx & 3;
            *(uint4*)(db + OBh + r * RS + c * 16) =
                *(const uint4*)((const char*)pBh + ((size_t)r * K) * 2 + c * 16);
            *(uint4*)(db + OBl + r * RS + c * 16) =
                *(const uint4*)((const char*)pBl + ((size_t)r * K) * 2 + c * 16);
        }
    }
    __syncthreads();

    for (int cch = 0; cch < NC; ++cch) {
        const int b = cch & 1;
        const uint32_t sb = sbase + b * SBUF;

        // prefetch next chunk into registers
        uint4 fAh[2], fAl[2], fBh[NBCH], fBl[NBCH];
        if (cch + 1 < NC) {
            const size_t k0b = (size_t)(cch + 1) * 32 * 2;
#pragma unroll
            for (int i = 0; i < 2; ++i) {
                int idx = tid + i * 256;
                int r = idx >> 2, c = idx & 3;
                fAh[i] = *(const uint4*)((const char*)pAh + (size_t)r * K * 2 + k0b + c * 16);
                fAl[i] = *(const uint4*)((const char*)pAl + (size_t)r * K * 2 + k0b + c * 16);
            }
#pragma unroll
            for (int i = 0; i < NBCH; ++i) {
                int idx = tid + i * 256;
                int r = idx >> 2, c = idx & 3;
                fBh[i] = *(const uint4*)((const char*)pBh + (size_t)r * K * 2 + k0b + c * 16);
                fBl[i] = *(const uint4*)((const char*)pBl + (size_t)r * K * 2 + k0b + c * 16);
            }
        }

        // compute on buffer b
#pragma unroll
        for (int ks = 0; ks < 2; ++ks) {
            uint32_t ah[2][4], al[2][4], bh[NBF][4], bl[NBF][4];
#pragma unroll
            for (int im = 0; im < 2; ++im) {
                uint32_t ra = sb + (warp_m * 32 + im * 16 + rowA) * RS + ks * 32 + colA;
                LDSM4(ah[im], ra);
                LDSM4(al[im], ra + OAl);
            }
#pragma unroll
            for (int ib = 0; ib < NBF; ++ib) {
                uint32_t rb = sb + OBh + (warp_n * WN + ib * 16 + rowB) * RS + ks * 32 + colB;
                LDSM4(bh[ib], rb);
                LDSM4(bl[ib], rb + (OBl - OBh));
            }
#pragma unroll
            for (int im = 0; im < 2; ++im)
#pragma unroll
                for (int j = 0; j < NJ; ++j) {
                    const int f = j >> 1, h = (j & 1) * 2;
                    MMA16816(acc[im][j], ah[im], bh[f][h], bh[f][h + 1]);
                    MMA16816(acc[im][j], ah[im], bl[f][h], bl[f][h + 1]);
                    MMA16816(acc[im][j], al[im], bh[f][h], bh[f][h + 1]);
                }
        }

        // store prefetched chunk into other buffer
        if (cch + 1 < NC) {
            char* db = smem + (b ^ 1) * SBUF;
#pragma unroll
            for (int i = 0; i < 2; ++i) {
                int idx = tid + i * 256;
                int r = idx >> 2, c = idx & 3;
                *(uint4*)(db + r * RS + c * 16) = fAh[i];
                *(uint4*)(db + OAl + r * RS + c * 16) = fAl[i];
            }
#pragma unroll
            for (int i = 0; i < NBCH; ++i) {
                int idx = tid + i * 256;
                int r = idx >> 2, c = idx & 3;
                *(uint4*)(db + OBh + r * RS + c * 16) = fBh[i];
                *(uint4*)(db + OBl + r * RS + c * 16) = fBl[i];
            }
            __syncthreads();
        }
    }

    // epilogue
#pragma unroll
    for (int im = 0; im < 2; ++im)
#pragma unroll
        for (int j = 0; j < NJ; ++j) {
            int row = m0 + warp_m * 32 + im * 16 + (lane >> 2);
            int col = n0 + warp_n * WN + j * 8 + (lane & 3) * 2;
            *(float2*)(C + (size_t)row * N + col) = make_float2(acc[im][j][0], acc[im][j][1]);
            *(float2*)(C + (size_t)(row + 8) * N + col) = make_float2(acc[im][j][2], acc[im][j][3]);
        }
}

// ---------------------------------------------------------------------------
// RoPE: fp64 angle + range reduction, fp32 sincos, loop over head blocks.
// ---------------------------------------------------------------------------
__global__ void rope_kernel(float* __restrict__ buf, int nblk) {
    int idx = blockIdx.x * blockDim.x + threadIdx.x;
    if (idx >= N_TOK * 64) return;
    int t = idx >> 6, i = idx & 63;
    double inv = exp(-9.210340371976184 * ((double)i / 64.0));
    double ang = (double)t * inv;
    double k = floor(ang * 0.15915494309189535);
    float r = (float)(ang - k * 6.283185307179586);
    float s, c;
    sincosf(r, &s, &c);
    float* p = buf + (size_t)t * (nblk * 128) + 2 * i;
#pragma unroll 4
    for (int b = 0; b < nblk; ++b, p += 128) {
        float xe = p[0], xo = p[1];
        p[0] = xe * c - xo * s;
        p[1] = xe * s + xo * c;
    }
}

// ---------------------------------------------------------------------------
// Flash attention, causal, fp32 (unchanged, proven in R1).
// ---------------------------------------------------------------------------
__global__ void __launch_bounds__(256) flash_kernel(const float* __restrict__ Q,
                                                    const float* __restrict__ Kb,
                                                    const float* __restrict__ Vb,
                                                    float* __restrict__ ctx) {
    const int qt = blockIdx.x;
    const int h  = blockIdx.y;
    const int g  = h >> 2, kv = h & 3;
    const int qcol0 = g * 512 + kv * 128;
    const int kcol0 = kv * 128;
    const int ocol0 = (kv * 4 + g) * 128;

    extern __shared__ float sm[];
    float* Qt       = sm;
    float* Kt       = Qt + 128 * 64;
    float* Vs       = Kt + 128 * 64;
    float* S        = Vs + 64 * 128;
    float* rowM     = S + 64 * 65;
    float* rowL     = rowM + 64;
    float* rowScale = rowL + 64;

    const int tid = threadIdx.x;
    const int tr  = tid >> 4, tc = tid & 15;
    const int i0  = tr * 4;
    const float SCALE = 0.08838834764831845f;

#pragma unroll
    for (int it = 0; it < 8; ++it) {
        int e = (it * 256 + tid) * 4;
        int rr = e >> 7, cc = e & 127;
        float4 v = *(const float4*)(Q + (size_t)(qt * 64 + rr) * 2048 + qcol0 + cc);
        Qt[(cc + 0) * 64 + rr] = v.x;
        Qt[(cc + 1) * 64 + rr] = v.y;
        Qt[(cc + 2) * 64 + rr] = v.z;
        Qt[(cc + 3) * 64 + rr] = v.w;
    }
    if (tid < 64) { rowM[tid] = -INFINITY; rowL[tid] = 0.f; }

    float acc[4][8];
#pragma unroll
    for (int rr = 0; rr < 4; ++rr)
#pragma unroll
        for (int cc = 0; cc < 8; ++cc) acc[rr][cc] = 0.f;

    for (int kt = 0; kt <= qt; ++kt) {
        __syncthreads();
#pragma unroll
        for (int it = 0; it < 8; ++it) {
            int e = (it * 256 + tid) * 4;
            int rr = e >> 7, cc = e & 127;
            float4 kvv = *(const float4*)(Kb + (size_t)(kt * 64 + rr) * 512 + kcol0 + cc);
            Kt[(cc + 0) * 64 + rr] = kvv.x;
            Kt[(cc + 1) * 64 + rr] = kvv.y;
            Kt[(cc + 2) * 64 + rr] = kvv.z;
            Kt[(cc + 3) * 64 + rr] = kvv.w;
            *(float4*)(Vs + rr * 128 + cc) =
                *(const float4*)(Vb + (size_t)(kt * 64 + rr) * 512 + kcol0 + cc);
        }
        __syncthreads();

        float sacc[4][4];
#pragma unroll
        for (int i = 0; i < 4; ++i)
#pragma unroll
            for (int j = 0; j < 4; ++j) sacc[i][j] = 0.f;
#pragma unroll 4
        for (int dd = 0; dd < 128; ++dd) {
            float4 a = *(const float4*)(Qt + dd * 64 + i0);
            float4 b = *(const float4*)(Kt + dd * 64 + tc * 4);
            float ra[4] = {a.x, a.y, a.z, a.w};
            float rb[4] = {b.x, b.y, b.z, b.w};
#pragma unroll
            for (int i = 0; i < 4; ++i)
#pragma unroll
                for (int j = 0; j < 4; ++j)
                    sacc[i][j] = fmaf(ra[i], rb[j], sacc[i][j]);
        }
#pragma unroll
        for (int i = 0; i < 4; ++i)
#pragma unroll
            for (int j = 0; j < 4; ++j) {
                float sv = sacc[i][j] * SCALE;
                if (kt == qt && (tc * 4 + j) > (i0 + i)) sv = -INFINITY;
                S[(i0 + i) * 65 + tc * 4 + j] = sv;
            }
        __syncthreads();

        if (tid < 64) {
            float mo = rowM[tid];
            float mx = mo;
#pragma unroll 8
            for (int j = 0; j < 64; ++j) mx = fmaxf(mx, S[tid * 65 + j]);
            float sc = expf(mo - mx);
            float sum = 0.f;
#pragma unroll 8
            for (int j = 0; j < 64; ++j) {
                float pv = expf(S[tid * 65 + j] - mx);
                S[tid * 65 + j] = pv;
                sum += pv;
            }
            rowL[tid]     = rowL[tid] * sc + sum;
            rowM[tid]     = mx;
            rowScale[tid] = sc;
        }
        __syncthreads();

#pragma unroll
        for (int rr = 0; rr < 4; ++rr) {
            float sc = rowScale[i0 + rr];
#pragma unroll
            for (int cc = 0; cc < 8; ++cc) acc[rr][cc] *= sc;
        }
#pragma unroll 2
        for (int j = 0; j < 64; ++j) {
            float p0 = S[(i0 + 0) * 65 + j];
            float p1 = S[(i0 + 1) * 65 + j];
            float p2 = S[(i0 + 2) * 65 + j];
            float p3 = S[(i0 + 3) * 65 + j];
            float4 v0 = *(const float4*)(Vs + j * 128 + tc * 8);
            float4 v1 = *(const float4*)(Vs + j * 128 + tc * 8 + 4);
            float vv[8] = {v0.x, v0.y, v0.z, v0.w, v1.x, v1.y, v1.z, v1.w};
#pragma unroll
            for (int cc = 0; cc < 8; ++cc) {
                acc[0][cc] = fmaf(p0, vv[cc], acc[0][cc]);
                acc[1][cc] = fmaf(p1, vv[cc], acc[1][cc]);
                acc[2][cc] = fmaf(p2, vv[cc], acc[2][cc]);
                acc[3][cc] = fmaf(p3, vv[cc], acc[3][cc]);
            }
        }
    }

#pragma unroll
    for (int rr = 0; rr < 4; ++rr) {
        float inv = 1.f / rowL[i0 + rr];
        float* dst = ctx + (size_t)(qt * 64 + i0 + rr) * 2048 + ocol0 + tc * 8;
        *(float4*)(dst)     = make_float4(acc[rr][0] * inv, acc[rr][1] * inv,
                                          acc[rr][2] * inv, acc[rr][3] * inv);
        *(float4*)(dst + 4) = make_float4(acc[rr][4] * inv, acc[rr][5] * inv,
                                          acc[rr][6] * inv, acc[rr][7] * inv);
    }
}

// ---------------------------------------------------------------------------
extern "C" void kernel_launch(void* const* d_in, const int* in_sizes, int n_in,
                              void* d_out, int out_size) {
    const float* x  = (const float*)d_in[0];
    const float* Wq = (const float*)d_in[1];
    const float* Wk = (const float*)d_in[2];
    const float* Wv = (const float*)d_in[3];
    const float* Wo = (const float*)d_in[4];
    float* out = (float*)d_out;

    float *Qb, *Kb, *Vb, *Cb;
    cudaGetSymbolAddress((void**)&Qb, g_Q);
    cudaGetSymbolAddress((void**)&Kb, g_K);
    cudaGetSymbolAddress((void**)&Vb, g_V);
    cudaGetSymbolAddress((void**)&Cb, g_ctx);
    __nv_bfloat16 *xh, *xl, *ch, *cl, *qth, *qtl, *kth, *ktl, *vth, *vtl, *oth, *otl;
    cudaGetSymbolAddress((void**)&xh, g_xh);   cudaGetSymbolAddress((void**)&xl, g_xl);
    cudaGetSymbolAddress((void**)&ch, g_ch);   cudaGetSymbolAddress((void**)&cl, g_cl);
    cudaGetSymbolAddress((void**)&qth, g_WqTh); cudaGetSymbolAddress((void**)&qtl, g_WqTl);
    cudaGetSymbolAddress((void**)&kth, g_WkTh); cudaGetSymbolAddress((void**)&ktl, g_WkTl);
    cudaGetSymbolAddress((void**)&vth, g_WvTh); cudaGetSymbolAddress((void**)&vtl, g_WvTl);
    cudaGetSymbolAddress((void**)&oth, g_WoTh); cudaGetSymbolAddress((void**)&otl, g_WoTl);

    // dynamic smem sizes: 2 buffers of (2*128 + 2*BN) * 80 bytes
    const int smem128 = 2 * (2 * 128 * 80 + 2 * 128 * 80);  // 81920
    const int smem64  = 2 * (2 * 128 * 80 + 2 * 64 * 80);   // 61440
    cudaFuncSetAttribute(hgemm3<128>, cudaFuncAttributeMaxDynamicSharedMemorySize, smem128);
    cudaFuncSetAttribute(hgemm3<64>,  cudaFuncAttributeMaxDynamicSharedMemorySize, smem64);

    // split inputs
    conv_act<<<(N_TOK * D_MODEL / 4 + 255) / 256, 256>>>(x, xh, xl, N_TOK * D_MODEL);
    conv_wT<<<dim3(D_MODEL / 32, D_MODEL / 32), dim3(32, 8)>>>(Wq, qth, qtl, D_MODEL, D_MODEL);
    conv_wT<<<dim3(KV_D / 32, D_MODEL / 32), dim3(32, 8)>>>(Wk, kth, ktl, D_MODEL, KV_D);
    conv_wT<<<dim3(KV_D / 32, D_MODEL / 32), dim3(32, 8)>>>(Wv, vth, vtl, D_MODEL, KV_D);
    conv_wT<<<dim3(D_MODEL / 32, D_MODEL / 32), dim3(32, 8)>>>(Wo, oth, otl, D_MODEL, D_MODEL);

    // projections (tensor cores, bf16x3 split)
    hgemm3<128><<<dim3(D_MODEL / 128, N_TOK / 128), 256, smem128>>>(xh, xl, qth, qtl, Qb, D_MODEL, D_MODEL);
    hgemm3<64><<<dim3(KV_D / 64, N_TOK / 128), 256, smem64>>>(xh, xl, kth, ktl, Kb, KV_D, D_MODEL);
    hgemm3<64><<<dim3(KV_D / 64, N_TOK / 128), 256, smem64>>>(xh, xl, vth, vtl, Vb, KV_D, D_MODEL);

    // RoPE
    rope_kernel<<<(N_TOK * 64 + 127) / 128, 128>>>(Qb, 16);
    rope_kernel<<<(N_TOK * 64 + 127) / 128, 128>>>(Kb, 4);

    // attention
    size_t fsmem = (size_t)(128 * 64 * 2 + 64 * 128 + 64 * 65 + 192) * sizeof(float);
    cudaFuncSetAttribute(flash_kernel, cudaFuncAttributeMaxDynamicSharedMemorySize, (int)fsmem);
    flash_kernel<<<dim3(N_TOK / 64, 16), 256, fsmem>>>(Qb, Kb, Vb, Cb);

    // output projection
    conv_act<<<(N_TOK * D_MODEL / 4 + 255) / 256, 256>>>(Cb, ch, cl, N_TOK * D_MODEL);
    hgemm3<128><<<dim3(D_MODEL / 128, N_TOK / 128), 256, smem128>>>(ch, cl, oth, otl, out, D_MODEL, D_MODEL);

    (void)in_sizes; (void)n_in; (void)out_size;
}

// round 4
// speedup vs baseline: 3.9127x; 2.1262x over previous
#include <cuda_runtime.h>
#include <cuda_bf16.h>
#include <math.h>
#include <stdint.h>

#define N_TOK   2048
#define D_MODEL 2048
#define KV_D    512

// ---------------- scratch (device globals: allocation-guard safe) ----------
__device__ float g_Q[N_TOK * D_MODEL];
__device__ float g_K[N_TOK * KV_D];
__device__ float g_V[N_TOK * KV_D];

__device__ __nv_bfloat16 g_xh[N_TOK * D_MODEL];
__device__ __nv_bfloat16 g_xl[N_TOK * D_MODEL];
__device__ __nv_bfloat16 g_ch[N_TOK * D_MODEL];
__device__ __nv_bfloat16 g_cl[N_TOK * D_MODEL];
__device__ __nv_bfloat16 g_Qh[N_TOK * D_MODEL];
__device__ __nv_bfloat16 g_Ql[N_TOK * D_MODEL];
__device__ __nv_bfloat16 g_Kh[N_TOK * KV_D];
__device__ __nv_bfloat16 g_Kl[N_TOK * KV_D];
__device__ __nv_bfloat16 g_Vth[KV_D * N_TOK];   // [kv][d][n]
__device__ __nv_bfloat16 g_Vtl[KV_D * N_TOK];
__device__ __nv_bfloat16 g_WqTh[D_MODEL * D_MODEL];
__device__ __nv_bfloat16 g_WqTl[D_MODEL * D_MODEL];
__device__ __nv_bfloat16 g_WkTh[KV_D * D_MODEL];
__device__ __nv_bfloat16 g_WkTl[KV_D * D_MODEL];
__device__ __nv_bfloat16 g_WvTh[KV_D * D_MODEL];
__device__ __nv_bfloat16 g_WvTl[KV_D * D_MODEL];
__device__ __nv_bfloat16 g_WoTh[D_MODEL * D_MODEL];
__device__ __nv_bfloat16 g_WoTl[D_MODEL * D_MODEL];

__device__ __forceinline__ uint32_t smem_u32(const void* p) {
    uint32_t a;
    asm("{ .reg .u64 t; cvta.to.shared.u64 t, %1; cvt.u32.u64 %0, t; }"
        : "=r"(a) : "l"(p));
    return a;
}

#define LDSM4(r, addr)                                                        \
    asm volatile("ldmatrix.sync.aligned.m8n8.x4.shared.b16 {%0,%1,%2,%3}, [%4];" \
                 : "=r"((r)[0]), "=r"((r)[1]), "=r"((r)[2]), "=r"((r)[3])     \
                 : "r"(addr))

#define MMA16816(d, a, b0, b1)                                                \
    asm volatile("mma.sync.aligned.m16n8k16.row.col.f32.bf16.bf16.f32 "       \
                 "{%0,%1,%2,%3}, {%4,%5,%6,%7}, {%8,%9}, {%0,%1,%2,%3};"      \
                 : "+f"((d)[0]), "+f"((d)[1]), "+f"((d)[2]), "+f"((d)[3])     \
                 : "r"((a)[0]), "r"((a)[1]), "r"((a)[2]), "r"((a)[3]),        \
                   "r"(b0), "r"(b1))

// e^x for x <= 0, FMA-pipe only (degree-6 2^f poly, ~1e-5 rel err)
__device__ __forceinline__ float fexp(float x) {
    float t = x * 1.4426950408889634f;
    t = fmaxf(t, -126.0f);
    float n = floorf(t);
    float f = t - n;
    float p = 1.5403530393283621e-4f;
    p = fmaf(p, f, 1.3333558146428443e-3f);
    p = fmaf(p, f, 9.6181291076284772e-3f);
    p = fmaf(p, f, 5.5504108664821580e-2f);
    p = fmaf(p, f, 2.4022650695910071e-1f);
    p = fmaf(p, f, 6.9314718055994531e-1f);
    p = fmaf(p, f, 1.0f);
    return __int_as_float(((int)n + 127) << 23) * p;
}

// ---------------------------------------------------------------------------
// Split/convert kernels
// ---------------------------------------------------------------------------
__global__ void conv_act(const float* __restrict__ in,
                         __nv_bfloat16* __restrict__ oh,
                         __nv_bfloat16* __restrict__ ol, int n) {
    int i = (blockIdx.x * blockDim.x + threadIdx.x) * 4;
    if (i >= n) return;
    float4 v = *(const float4*)(in + i);
    __nv_bfloat16 h0 = __float2bfloat16(v.x);
    __nv_bfloat16 h1 = __float2bfloat16(v.y);
    __nv_bfloat16 h2 = __float2bfloat16(v.z);
    __nv_bfloat16 h3 = __float2bfloat16(v.w);
    __nv_bfloat16 l0 = __float2bfloat16(v.x - __bfloat162float(h0));
    __nv_bfloat16 l1 = __float2bfloat16(v.y - __bfloat162float(h1));
    __nv_bfloat16 l2 = __float2bfloat16(v.z - __bfloat162float(h2));
    __nv_bfloat16 l3 = __float2bfloat16(v.w - __bfloat162float(h3));
    __nv_bfloat162* ph = (__nv_bfloat162*)(oh + i);
    __nv_bfloat162* pl = (__nv_bfloat162*)(ol + i);
    ph[0] = __nv_bfloat162(h0, h1); ph[1] = __nv_bfloat162(h2, h3);
    pl[0] = __nv_bfloat162(l0, l1); pl[1] = __nv_bfloat162(l2, l3);
}

// W [Kdim, Ndim] fp32 -> WT [Ndim, Kdim] hi/lo bf16
__global__ void conv_wT(const float* __restrict__ in,
                        __nv_bfloat16* __restrict__ oh,
                        __nv_bfloat16* __restrict__ ol, int Kdim, int Ndim) {
    __shared__ float t[32][33];
    int n0 = blockIdx.x * 32, k0 = blockIdx.y * 32;
    int tx = threadIdx.x, ty = threadIdx.y;
#pragma unroll
    for (int i = 0; i < 4; ++i)
        t[ty + 8 * i][tx] = in[(size_t)(k0 + ty + 8 * i) * Ndim + n0 + tx];
    __syncthreads();
#pragma unroll
    for (int i = 0; i < 4; ++i) {
        int nl = ty + 8 * i;
        float v = t[tx][nl];
        __nv_bfloat16 h = __float2bfloat16(v);
        __nv_bfloat16 l = __float2bfloat16(v - __bfloat162float(h));
        size_t o = (size_t)(n0 + nl) * Kdim + k0 + tx;
        oh[o] = h; ol[o] = l;
    }
}

// RoPE + bf16 split: fp32 in -> hi/lo bf16 out (rotated)
__global__ void rope_conv(const float* __restrict__ in,
                          __nv_bfloat16* __restrict__ oh,
                          __nv_bfloat16* __restrict__ ol, int nblk) {
    int idx = blockIdx.x * blockDim.x + threadIdx.x;
    if (idx >= N_TOK * 64) return;
    int t = idx >> 6, i = idx & 63;
    double inv = exp(-9.210340371976184 * ((double)i / 64.0));
    double ang = (double)t * inv;
    double k = floor(ang * 0.15915494309189535);
    float r = (float)(ang - k * 6.283185307179586);
    float s, c;
    sincosf(r, &s, &c);
    const int cols = nblk * 128;
    const float* p = in + (size_t)t * cols + 2 * i;
#pragma unroll 4
    for (int b = 0; b < nblk; ++b) {
        float xe = p[b * 128], xo = p[b * 128 + 1];
        float oe = xe * c - xo * s;
        float oo = xe * s + xo * c;
        __nv_bfloat16 he = __float2bfloat16(oe);
        __nv_bfloat16 ho = __float2bfloat16(oo);
        __nv_bfloat16 le = __float2bfloat16(oe - __bfloat162float(he));
        __nv_bfloat16 lo = __float2bfloat16(oo - __bfloat162float(ho));
        size_t o = (size_t)t * cols + b * 128 + 2 * i;
        *(__nv_bfloat162*)(oh + o) = __nv_bfloat162(he, ho);
        *(__nv_bfloat162*)(ol + o) = __nv_bfloat162(le, lo);
    }
}

// V fp32 [N, 512] -> per-head transposed Vt hi/lo [kv][d=128][N]
__global__ void conv_vT(const float* __restrict__ in,
                        __nv_bfloat16* __restrict__ oh,
                        __nv_bfloat16* __restrict__ ol) {
    __shared__ float t[32][33];
    int n0 = blockIdx.x * 32, c0 = blockIdx.y * 32;
    int tx = threadIdx.x, ty = threadIdx.y;
#pragma unroll
    for (int i = 0; i < 4; ++i)
        t[ty + 8 * i][tx] = in[(size_t)(n0 + ty + 8 * i) * KV_D + c0 + tx];
    __syncthreads();
#pragma unroll
    for (int i = 0; i < 4; ++i) {
        int cl = ty + 8 * i;
        float v = t[tx][cl];                        // = in[n0+tx][c0+cl]
        int cglob = c0 + cl;
        int kv = cglob >> 7, d = cglob & 127;
        size_t o = (size_t)kv * 128 * N_TOK + (size_t)d * N_TOK + n0 + tx;
        __nv_bfloat16 h = __float2bfloat16(v);
        oh[o] = h;
        ol[o] = __float2bfloat16(v - __bfloat162float(h));
    }
}

// ---------------------------------------------------------------------------
// bf16x3-split HGEMM (mma.sync): C = A @ Bt^T  (unchanged from R3, proven)
// ---------------------------------------------------------------------------
template <int BN>
__global__ void __launch_bounds__(256) hgemm3(
    const __nv_bfloat16* __restrict__ Ah, const __nv_bfloat16* __restrict__ Al,
    const __nv_bfloat16* __restrict__ Bh, const __nv_bfloat16* __restrict__ Bl,
    float* __restrict__ C, int N, int K) {
    constexpr int BM = 128;
    constexpr int WN = BN / 2;
    constexpr int NBF = WN / 16;
    constexpr int NJ = WN / 8;
    constexpr int RS = 80;
    constexpr int OAl = BM * RS;
    constexpr int OBh = 2 * BM * RS;
    constexpr int OBl = 2 * BM * RS + BN * RS;
    constexpr int SBUF = 2 * BM * RS + 2 * BN * RS;
    constexpr int NBCH = BN * 4 / 256;

    extern __shared__ char smem[];
    const uint32_t sbase = smem_u32(smem);

    const int tid = threadIdx.x;
    const int lane = tid & 31;
    const int wid = tid >> 5;
    const int warp_m = wid & 3;
    const int warp_n = wid >> 2;

    const int m0 = blockIdx.y * BM;
    const int n0 = blockIdx.x * BN;
    const __nv_bfloat16* pAh = Ah + (size_t)m0 * K;
    const __nv_bfloat16* pAl = Al + (size_t)m0 * K;
    const __nv_bfloat16* pBh = Bh + (size_t)n0 * K;
    const __nv_bfloat16* pBl = Bl + (size_t)n0 * K;

    const int q = lane >> 3;
    const int rowA = (lane & 7) + (q & 1) * 8;
    const int colA = (q >> 1) * 16;
    const int rowB = (lane & 7) + (q >> 1) * 8;
    const int colB = (q & 1) * 16;

    float acc[2][NJ][4];
#pragma unroll
    for (int im = 0; im < 2; ++im)
#pragma unroll
        for (int j = 0; j < NJ; ++j)
#pragma unroll
            for (int e = 0; e < 4; ++e) acc[im][j][e] = 0.f;

    const int NC = K / 32;
    {
        char* db = smem;
#pragma unroll
        for (int i = 0; i < 2; ++i) {
            int idx = tid + i * 256;
            int r = idx >> 2, c = idx & 3;
            *(uint4*)(db + r * RS + c * 16) =
                *(const uint4*)((const char*)pAh + ((size_t)r * K) * 2 + c * 16);
            *(uint4*)(db + OAl + r * RS + c * 16) =
                *(const uint4*)((const char*)pAl + ((size_t)r * K) * 2 + c * 16);
        }
#pragma unroll
        for (int i = 0; i < NBCH; ++i) {
            int idx = tid + i * 256;
            int r = idx >> 2, c = idx & 3;
            *(uint4*)(db + OBh + r * RS + c * 16) =
                *(const uint4*)((const char*)pBh + ((size_t)r * K) * 2 + c * 16);
            *(uint4*)(db + OBl + r * RS + c * 16) =
                *(const uint4*)((const char*)pBl + ((size_t)r * K) * 2 + c * 16);
        }
    }
    __syncthreads();

    for (int cch = 0; cch < NC; ++cch) {
        const int b = cch & 1;
        const uint32_t sb = sbase + b * SBUF;

        uint4 fAh[2], fAl[2], fBh[NBCH], fBl[NBCH];
        if (cch + 1 < NC) {
            const size_t k0b = (size_t)(cch + 1) * 32 * 2;
#pragma unroll
            for (int i = 0; i < 2; ++i) {
                int idx = tid + i * 256;
                int r = idx >> 2, c = idx & 3;
                fAh[i] = *(const uint4*)((const char*)pAh + (size_t)r * K * 2 + k0b + c * 16);
                fAl[i] = *(const uint4*)((const char*)pAl + (size_t)r * K * 2 + k0b + c * 16);
            }
#pragma unroll
            for (int i = 0; i < NBCH; ++i) {
                int idx = tid + i * 256;
                int r = idx >> 2, c = idx & 3;
                fBh[i] = *(const uint4*)((const char*)pBh + (size_t)r * K * 2 + k0b + c * 16);
                fBl[i] = *(const uint4*)((const char*)pBl + (size_t)r * K * 2 + k0b + c * 16);
            }
        }

#pragma unroll
        for (int ks = 0; ks < 2; ++ks) {
            uint32_t ah[2][4], al[2][4], bh[NBF][4], bl[NBF][4];
#pragma unroll
            for (int im = 0; im < 2; ++im) {
                uint32_t ra = sb + (warp_m * 32 + im * 16 + rowA) * RS + ks * 32 + colA;
                LDSM4(ah[im], ra);
                LDSM4(al[im], ra + OAl);
            }
#pragma unroll
            for (int ib = 0; ib < NBF; ++ib) {
                uint32_t rb = sb + OBh + (warp_n * WN + ib * 16 + rowB) * RS + ks * 32 + colB;
                LDSM4(bh[ib], rb);
                LDSM4(bl[ib], rb + (OBl - OBh));
            }
#pragma unroll
            for (int im = 0; im < 2; ++im)
#pragma unroll
                for (int j = 0; j < NJ; ++j) {
                    const int f = j >> 1, h = (j & 1) * 2;
                    MMA16816(acc[im][j], ah[im], bh[f][h], bh[f][h + 1]);
                    MMA16816(acc[im][j], ah[im], bl[f][h], bl[f][h + 1]);
                    MMA16816(acc[im][j], al[im], bh[f][h], bh[f][h + 1]);
                }
        }

        if (cch + 1 < NC) {
            char* db = smem + (b ^ 1) * SBUF;
#pragma unroll
            for (int i = 0; i < 2; ++i) {
                int idx = tid + i * 256;
                int r = idx >> 2, c = idx & 3;
                *(uint4*)(db + r * RS + c * 16) = fAh[i];
                *(uint4*)(db + OAl + r * RS + c * 16) = fAl[i];
            }
#pragma unroll
            for (int i = 0; i < NBCH; ++i) {
                int idx = tid + i * 256;
                int r = idx >> 2, c = idx & 3;
                *(uint4*)(db + OBh + r * RS + c * 16) = fBh[i];
                *(uint4*)(db + OBl + r * RS + c * 16) = fBl[i];
            }
            __syncthreads();
        }
    }

#pragma unroll
    for (int im = 0; im < 2; ++im)
#pragma unroll
        for (int j = 0; j < NJ; ++j) {
            int row = m0 + warp_m * 32 + im * 16 + (lane >> 2);
            int col = n0 + warp_n * WN + j * 8 + (lane & 3) * 2;
            *(float2*)(C + (size_t)row * N + col) = make_float2(acc[im][j][0], acc[im][j][1]);
            *(float2*)(C + (size_t)(row + 8) * N + col) = make_float2(acc[im][j][2], acc[im][j][3]);
        }
}

// ---------------------------------------------------------------------------
// Tensor-core flash attention, causal, bf16x3 split, fp32 softmax.
// BM=128 q rows x BN=64 keys per tile, 8 warps (16 rows each).
// grid (16 qtiles reversed, 16 heads), 256 threads.
// ---------------------------------------------------------------------------
#define RSQ 272
#define RSV 144
#define OQH 0
#define OQL (OQH + 128 * RSQ)
#define OKH (OQL + 128 * RSQ)
#define OKL (OKH + 64 * RSQ)
#define OVH (OKL + 64 * RSQ)
#define OVL (OVH + 128 * RSV)
#define OPH (OVL + 128 * RSV)
#define OPL (OPH + 128 * RSV)
#define FSMEM (OPL + 128 * RSV)

__global__ void __launch_bounds__(256, 1) flash_mma(
    const __nv_bfloat16* __restrict__ Qh, const __nv_bfloat16* __restrict__ Ql,
    const __nv_bfloat16* __restrict__ Kh, const __nv_bfloat16* __restrict__ Kl,
    const __nv_bfloat16* __restrict__ Vth, const __nv_bfloat16* __restrict__ Vtl,
    __nv_bfloat16* __restrict__ ch, __nv_bfloat16* __restrict__ cl) {
    const int qt = gridDim.x - 1 - blockIdx.x;   // big blocks first
    const int h  = blockIdx.y;
    const int g  = h >> 2, kv = h & 3;
    const int qcol0 = g * 512 + kv * 128;
    const int kcol0 = kv * 128;
    const int ocol0 = (kv * 4 + g) * 128;
    const __nv_bfloat16* vh = Vth + (size_t)kv * 128 * N_TOK;
    const __nv_bfloat16* vl = Vtl + (size_t)kv * 128 * N_TOK;

    extern __shared__ char smem[];
    const uint32_t sbase = smem_u32(smem);

    const int tid = threadIdx.x;
    const int lane = tid & 31;
    const int warp_m = tid >> 5;                 // 0..7
    const int q4 = lane >> 2, l4 = lane & 3;
    const int qq = lane >> 3;
    const int rowA = (lane & 7) + (qq & 1) * 8;
    const int colA = (qq >> 1) * 16;
    const int rowB = (lane & 7) + (qq >> 1) * 8;
    const int colB = (qq & 1) * 16;
    const float SCALE = 0.08838834764831845f;

    // ---- load Q tile (rows qt*128.., cols qcol0..+128), hi/lo
#pragma unroll
    for (int i = 0; i < 8; ++i) {
        int idx = tid + i * 256;
        int r = idx >> 4, c = idx & 15;
        size_t go = (size_t)(qt * 128 + r) * D_MODEL + qcol0 + c * 8;
        *(uint4*)(smem + OQH + r * RSQ + c * 16) = *(const uint4*)(Qh + go);
        *(uint4*)(smem + OQL + r * RSQ + c * 16) = *(const uint4*)(Ql + go);
    }

    float o[16][4];
#pragma unroll
    for (int f = 0; f < 16; ++f)
#pragma unroll
        for (int e = 0; e < 4; ++e) o[f][e] = 0.f;
    float m0 = -1e30f, m1 = -1e30f, l0 = 0.f, l1 = 0.f;

    const int nkt = 2 * qt + 2;
    for (int kt = 0; kt < nkt; ++kt) {
        __syncthreads();   // prior tile fully consumed (and Q stores on iter 0)
        // ---- load K tile + Vt tile (hi/lo)
#pragma unroll
        for (int i = 0; i < 4; ++i) {
            int idx = tid + i * 256;
            int r = idx >> 4, c = idx & 15;
            size_t go = (size_t)(kt * 64 + r) * KV_D + kcol0 + c * 8;
            *(uint4*)(smem + OKH + r * RSQ + c * 16) = *(const uint4*)(Kh + go);
            *(uint4*)(smem + OKL + r * RSQ + c * 16) = *(const uint4*)(Kl + go);
        }
#pragma unroll
        for (int i = 0; i < 4; ++i) {
            int idx = tid + i * 256;
            int r = idx >> 3, c = idx & 7;
            size_t go = (size_t)r * N_TOK + kt * 64 + c * 8;
            *(uint4*)(smem + OVH + r * RSV + c * 16) = *(const uint4*)(vh + go);
            *(uint4*)(smem + OVL + r * RSV + c * 16) = *(const uint4*)(vl + go);
        }
        __syncthreads();

        const int rbase = qt * 128 + warp_m * 16;          // warp's first q row
        const bool active = (kt * 64) <= (rbase + 15);     // any key visible?
        float corr0 = 1.f, corr1 = 1.f;

        if (active) {
            // ---- S = Q K^T (16 x 64 per warp), 3-split
            float sacc[8][4];
#pragma unroll
            for (int j = 0; j < 8; ++j)
#pragma unroll
                for (int e = 0; e < 4; ++e) sacc[j][e] = 0.f;
#pragma unroll
            for (int ks = 0; ks < 8; ++ks) {
                uint32_t ah[4], al[4], bh[4], bl[4];
                uint32_t ra = sbase + OQH + (warp_m * 16 + rowA) * RSQ + ks * 32 + colA;
                LDSM4(ah, ra);
                LDSM4(al, ra + (OQL - OQH));
#pragma unroll
                for (int ib = 0; ib < 4; ++ib) {
                    uint32_t rb = sbase + OKH + (ib * 16 + rowB) * RSQ + ks * 32 + colB;
                    LDSM4(bh, rb);
                    LDSM4(bl, rb + (OKL - OKH));
#pragma unroll
                    for (int half = 0; half < 2; ++half) {
                        MMA16816(sacc[ib * 2 + half], ah, bh[half * 2], bh[half * 2 + 1]);
                        MMA16816(sacc[ib * 2 + half], ah, bl[half * 2], bl[half * 2 + 1]);
                        MMA16816(sacc[ib * 2 + half], al, bh[half * 2], bh[half * 2 + 1]);
                    }
                }
            }
            // ---- scale + causal mask
            const bool needMask = (kt * 64 + 63) > rbase;
#pragma unroll
            for (int j = 0; j < 8; ++j)
#pragma unroll
                for (int e = 0; e < 4; ++e) {
                    float v = sacc[j][e] * SCALE;
                    if (needMask) {
                        int rg = rbase + q4 + (e >> 1) * 8;
                        int kg = kt * 64 + j * 8 + l4 * 2 + (e & 1);
                        if (kg > rg) v = -1e30f;
                    }
                    sacc[j][e] = v;
                }
            // ---- row max (in-warp: lanes l4 share a row)
            float mx0 = -1e30f, mx1 = -1e30f;
#pragma unroll
            for (int j = 0; j < 8; ++j) {
                mx0 = fmaxf(mx0, fmaxf(sacc[j][0], sacc[j][1]));
                mx1 = fmaxf(mx1, fmaxf(sacc[j][2], sacc[j][3]));
            }
            mx0 = fmaxf(mx0, __shfl_xor_sync(0xffffffffu, mx0, 1));
            mx0 = fmaxf(mx0, __shfl_xor_sync(0xffffffffu, mx0, 2));
            mx1 = fmaxf(mx1, __shfl_xor_sync(0xffffffffu, mx1, 1));
            mx1 = fmaxf(mx1, __shfl_xor_sync(0xffffffffu, mx1, 2));
            float nm0 = fmaxf(m0, mx0), nm1 = fmaxf(m1, mx1);
            corr0 = fexp(m0 - nm0); corr1 = fexp(m1 - nm1);
            m0 = nm0; m1 = nm1;
            // ---- P = exp(s - m), row sums, store split bf16 to smem
            float s0 = 0.f, s1 = 0.f;
            uint32_t prow0 = sbase + OPH + (warp_m * 16 + q4) * RSV + l4 * 4;
            uint32_t prow1 = prow0 + 8 * RSV;
#pragma unroll
            for (int j = 0; j < 8; ++j) {
                float p00 = fexp(sacc[j][0] - m0);
                float p01 = fexp(sacc[j][1] - m0);
                float p10 = fexp(sacc[j][2] - m1);
                float p11 = fexp(sacc[j][3] - m1);
                s0 += p00 + p01; s1 += p10 + p11;
                __nv_bfloat16 h00 = __float2bfloat16(p00);
                __nv_bfloat16 h01 = __float2bfloat16(p01);
                __nv_bfloat16 h10 = __float2bfloat16(p10);
                __nv_bfloat16 h11 = __float2bfloat16(p11);
                __nv_bfloat162 hp0(h00, h01), hp1(h10, h11);
                __nv_bfloat162 lp0(__float2bfloat16(p00 - __bfloat162float(h00)),
                                   __float2bfloat16(p01 - __bfloat162float(h01)));
                __nv_bfloat162 lp1(__float2bfloat16(p10 - __bfloat162float(h10)),
                                   __float2bfloat16(p11 - __bfloat162float(h11)));
                asm volatile("st.shared.b32 [%0], %1;" :: "r"(prow0 + j * 16), "r"(*(uint32_t*)&hp0));
                asm volatile("st.shared.b32 [%0], %1;" :: "r"(prow1 + j * 16), "r"(*(uint32_t*)&hp1));
                asm volatile("st.shared.b32 [%0], %1;" :: "r"(prow0 + (OPL - OPH) + j * 16), "r"(*(uint32_t*)&lp0));
                asm volatile("st.shared.b32 [%0], %1;" :: "r"(prow1 + (OPL - OPH) + j * 16), "r"(*(uint32_t*)&lp1));
            }
            s0 += __shfl_xor_sync(0xffffffffu, s0, 1);
            s0 += __shfl_xor_sync(0xffffffffu, s0, 2);
            s1 += __shfl_xor_sync(0xffffffffu, s1, 1);
            s1 += __shfl_xor_sync(0xffffffffu, s1, 2);
            l0 = l0 * corr0 + s0;
            l1 = l1 * corr1 + s1;
            // ---- rescale O
#pragma unroll
            for (int f = 0; f < 16; ++f) {
                o[f][0] *= corr0; o[f][1] *= corr0;
                o[f][2] *= corr1; o[f][3] *= corr1;
            }
        }
        __syncthreads();   // P visible to ldmatrix

        if (active) {
            // ---- O += P @ V  (A = P rows of this warp, B = Vt), 3-split
#pragma unroll
            for (int ks = 0; ks < 4; ++ks) {
                uint32_t pa[4], pl_[4];
                uint32_t raddr = sbase + OPH + (warp_m * 16 + rowA) * RSV + ks * 32 + colA;
                LDSM4(pa, raddr);
                LDSM4(pl_, raddr + (OPL - OPH));
#pragma unroll
                for (int ib = 0; ib < 4; ++ib) {
                    uint32_t vb[4], vbl[4];
                    uint32_t baddr = sbase + OVH + (ib * 32 + rowB * 2 - rowB + rowB) * RSV; // placeholder
                    baddr = sbase + OVH + (ib * 16 + rowB) * RSV + ks * 32 + colB;
                    (void)baddr;
                    uint32_t b0 = sbase + OVH + (ib * 16 + rowB) * RSV + ks * 32 + colB;
                    LDSM4(vb, b0);
                    LDSM4(vbl, b0 + (OVL - OVH));
#pragma unroll
                    for (int half = 0; half < 2; ++half) {
                        MMA16816(o[ib * 2 + half], pa, vb[half * 2], vb[half * 2 + 1]);
                        MMA16816(o[ib * 2 + half], pa, vbl[half * 2], vbl[half * 2 + 1]);
                        MMA16816(o[ib * 2 + half], pl_, vb[half * 2], vb[half * 2 + 1]);
                    }
                }
                // second half of d (n groups 4..7)
#pragma unroll
                for (int ib = 4; ib < 8; ++ib) {
                    uint32_t vb[4], vbl[4];
                    uint32_t b0 = sbase + OVH + (ib * 16 + rowB) * RSV + ks * 32 + colB;
                    LDSM4(vb, b0);
                    LDSM4(vbl, b0 + (OVL - OVH));
#pragma unroll
                    for (int half = 0; half < 2; ++half) {
                        MMA16816(o[ib * 2 + half], pa, vb[half * 2], vb[half * 2 + 1]);
                        MMA16816(o[ib * 2 + half], pa, vbl[half * 2], vbl[half * 2 + 1]);
                        MMA16816(o[ib * 2 + half], pl_, vb[half * 2], vb[half * 2 + 1]);
                    }
                }
            }
        }
    }

    // ---- epilogue: normalize and write split bf16 ctx
    float i0 = 1.f / l0, i1 = 1.f / l1;
    int row0 = qt * 128 + warp_m * 16 + q4;
#pragma unroll
    for (int f = 0; f < 16; ++f) {
        int col = ocol0 + f * 8 + l4 * 2;
        float c00 = o[f][0] * i0, c01 = o[f][1] * i0;
        float c10 = o[f][2] * i1, c11 = o[f][3] * i1;
        __nv_bfloat16 h00 = __float2bfloat16(c00), h01 = __float2bfloat16(c01);
        __nv_bfloat16 h10 = __float2bfloat16(c10), h11 = __float2bfloat16(c11);
        *(__nv_bfloat162*)(ch + (size_t)row0 * D_MODEL + col) = __nv_bfloat162(h00, h01);
        *(__nv_bfloat162*)(ch + (size_t)(row0 + 8) * D_MODEL + col) = __nv_bfloat162(h10, h11);
        *(__nv_bfloat162*)(cl + (size_t)row0 * D_MODEL + col) =
            __nv_bfloat162(__float2bfloat16(c00 - __bfloat162float(h00)),
                           __float2bfloat16(c01 - __bfloat162float(h01)));
        *(__nv_bfloat162*)(cl + (size_t)(row0 + 8) * D_MODEL + col) =
            __nv_bfloat162(__float2bfloat16(c10 - __bfloat162float(h10)),
                           __float2bfloat16(c11 - __bfloat162float(h11)));
    }
}

// ---------------------------------------------------------------------------
extern "C" void kernel_launch(void* const* d_in, const int* in_sizes, int n_in,
                              void* d_out, int out_size) {
    const float* x  = (const float*)d_in[0];
    const float* Wq = (const float*)d_in[1];
    const float* Wk = (const float*)d_in[2];
    const float* Wv = (const float*)d_in[3];
    const float* Wo = (const float*)d_in[4];
    float* out = (float*)d_out;

    float *Qb, *Kb, *Vb;
    cudaGetSymbolAddress((void**)&Qb, g_Q);
    cudaGetSymbolAddress((void**)&Kb, g_K);
    cudaGetSymbolAddress((void**)&Vb, g_V);
    __nv_bfloat16 *xh, *xl, *ch, *cl, *qh, *ql, *kh, *kl, *vth, *vtl;
    __nv_bfloat16 *qth, *qtl, *kth, *ktl, *vwh, *vwl, *oth, *otl;
    cudaGetSymbolAddress((void**)&xh, g_xh);   cudaGetSymbolAddress((void**)&xl, g_xl);
    cudaGetSymbolAddress((void**)&ch, g_ch);   cudaGetSymbolAddress((void**)&cl, g_cl);
    cudaGetSymbolAddress((void**)&qh, g_Qh);   cudaGetSymbolAddress((void**)&ql, g_Ql);
    cudaGetSymbolAddress((void**)&kh, g_Kh);   cudaGetSymbolAddress((void**)&kl, g_Kl);
    cudaGetSymbolAddress((void**)&vth, g_Vth); cudaGetSymbolAddress((void**)&vtl, g_Vtl);
    cudaGetSymbolAddress((void**)&qth, g_WqTh); cudaGetSymbolAddress((void**)&qtl, g_WqTl);
    cudaGetSymbolAddress((void**)&kth, g_WkTh); cudaGetSymbolAddress((void**)&ktl, g_WkTl);
    cudaGetSymbolAddress((void**)&vwh, g_WvTh); cudaGetSymbolAddress((void**)&vwl, g_WvTl);
    cudaGetSymbolAddress((void**)&oth, g_WoTh); cudaGetSymbolAddress((void**)&otl, g_WoTl);

    const int smem128 = 2 * (2 * 128 * 80 + 2 * 128 * 80);
    const int smem64  = 2 * (2 * 128 * 80 + 2 * 64 * 80);
    cudaFuncSetAttribute(hgemm3<128>, cudaFuncAttributeMaxDynamicSharedMemorySize, smem128);
    cudaFuncSetAttribute(hgemm3<64>,  cudaFuncAttributeMaxDynamicSharedMemorySize, smem64);
    cudaFuncSetAttribute(flash_mma, cudaFuncAttributeMaxDynamicSharedMemorySize, FSMEM);

    // split inputs
    conv_act<<<(N_TOK * D_MODEL / 4 + 255) / 256, 256>>>(x, xh, xl, N_TOK * D_MODEL);
    conv_wT<<<dim3(D_MODEL / 32, D_MODEL / 32), dim3(32, 8)>>>(Wq, qth, qtl, D_MODEL, D_MODEL);
    conv_wT<<<dim3(KV_D / 32, D_MODEL / 32), dim3(32, 8)>>>(Wk, kth, ktl, D_MODEL, KV_D);
    conv_wT<<<dim3(KV_D / 32, D_MODEL / 32), dim3(32, 8)>>>(Wv, vwh, vwl, D_MODEL, KV_D);
    conv_wT<<<dim3(D_MODEL / 32, D_MODEL / 32), dim3(32, 8)>>>(Wo, oth, otl, D_MODEL, D_MODEL);

    // projections
    hgemm3<128><<<dim3(D_MODEL / 128, N_TOK / 128), 256, smem128>>>(xh, xl, qth, qtl, Qb, D_MODEL, D_MODEL);
    hgemm3<64><<<dim3(KV_D / 64, N_TOK / 128), 256, smem64>>>(xh, xl, kth, ktl, Kb, KV_D, D_MODEL);
    hgemm3<64><<<dim3(KV_D / 64, N_TOK / 128), 256, smem64>>>(xh, xl, vwh, vwl, Vb, KV_D, D_MODEL);

    // RoPE + split conversions
    rope_conv<<<(N_TOK * 64 + 127) / 128, 128>>>(Qb, qh, ql, 16);
    rope_conv<<<(N_TOK * 64 + 127) / 128, 128>>>(Kb, kh, kl, 4);
    conv_vT<<<dim3(N_TOK / 32, KV_D / 32), dim3(32, 8)>>>(Vb, vth, vtl);

    // attention (tensor cores)
    flash_mma<<<dim3(N_TOK / 128, 16), 256, FSMEM>>>(qh, ql, kh, kl, vth, vtl, ch, cl);

    // output projection
    hgemm3<128><<<dim3(D_MODEL / 128, N_TOK / 128), 256, smem128>>>(ch, cl, oth, otl, out, D_MODEL, D_MODEL);

    (void)in_sizes; (void)n_in; (void)out_size;
}

// round 5
// speedup vs baseline: 4.1249x; 1.0542x over previous
#include <cuda_runtime.h>
#include <cuda_bf16.h>
#include <math.h>
#include <stdint.h>

#define N_TOK   2048
#define D_MODEL 2048
#define KV_D    512

// ---------------- scratch (device globals: allocation-guard safe) ----------
__device__ __nv_bfloat16 g_xh[N_TOK * D_MODEL];
__device__ __nv_bfloat16 g_xl[N_TOK * D_MODEL];
__device__ __nv_bfloat16 g_ch[N_TOK * D_MODEL];
__device__ __nv_bfloat16 g_cl[N_TOK * D_MODEL];
__device__ __nv_bfloat16 g_Qh[N_TOK * D_MODEL];
__device__ __nv_bfloat16 g_Ql[N_TOK * D_MODEL];
__device__ __nv_bfloat16 g_Kh[N_TOK * KV_D];
__device__ __nv_bfloat16 g_Kl[N_TOK * KV_D];
__device__ __nv_bfloat16 g_Vth[KV_D * N_TOK];   // [kv][d][n]
__device__ __nv_bfloat16 g_Vtl[KV_D * N_TOK];
__device__ __nv_bfloat16 g_WqTh[D_MODEL * D_MODEL];
__device__ __nv_bfloat16 g_WqTl[D_MODEL * D_MODEL];
__device__ __nv_bfloat16 g_WkTh[KV_D * D_MODEL];
__device__ __nv_bfloat16 g_WkTl[KV_D * D_MODEL];
__device__ __nv_bfloat16 g_WvTh[KV_D * D_MODEL];
__device__ __nv_bfloat16 g_WvTl[KV_D * D_MODEL];
__device__ __nv_bfloat16 g_WoTh[D_MODEL * D_MODEL];
__device__ __nv_bfloat16 g_WoTl[D_MODEL * D_MODEL];
__device__ float2 g_rope[N_TOK * 64];           // (cos, sin) per (token, pair)

__device__ __forceinline__ uint32_t smem_u32(const void* p) {
    uint32_t a;
    asm("{ .reg .u64 t; cvta.to.shared.u64 t, %1; cvt.u32.u64 %0, t; }"
        : "=r"(a) : "l"(p));
    return a;
}

#define LDSM4(r, addr)                                                        \
    asm volatile("ldmatrix.sync.aligned.m8n8.x4.shared.b16 {%0,%1,%2,%3}, [%4];" \
                 : "=r"((r)[0]), "=r"((r)[1]), "=r"((r)[2]), "=r"((r)[3])     \
                 : "r"(addr))

#define MMA16816(d, a, b0, b1)                                                \
    asm volatile("mma.sync.aligned.m16n8k16.row.col.f32.bf16.bf16.f32 "       \
                 "{%0,%1,%2,%3}, {%4,%5,%6,%7}, {%8,%9}, {%0,%1,%2,%3};"      \
                 : "+f"((d)[0]), "+f"((d)[1]), "+f"((d)[2]), "+f"((d)[3])     \
                 : "r"((a)[0]), "r"((a)[1]), "r"((a)[2]), "r"((a)[3]),        \
                   "r"(b0), "r"(b1))

// e^x for x <= 0, FMA-pipe only (degree-6 2^f poly, ~1e-5 rel err)
__device__ __forceinline__ float fexp(float x) {
    float t = x * 1.4426950408889634f;
    t = fmaxf(t, -126.0f);
    float n = floorf(t);
    float f = t - n;
    float p = 1.5403530393283621e-4f;
    p = fmaf(p, f, 1.3333558146428443e-3f);
    p = fmaf(p, f, 9.6181291076284772e-3f);
    p = fmaf(p, f, 5.5504108664821580e-2f);
    p = fmaf(p, f, 2.4022650695910071e-1f);
    p = fmaf(p, f, 6.9314718055994531e-1f);
    p = fmaf(p, f, 1.0f);
    return __int_as_float(((int)n + 127) << 23) * p;
}

__device__ __forceinline__ void split2(float a, float b, __nv_bfloat162& h,
                                       __nv_bfloat162& l) {
    __nv_bfloat16 ha = __float2bfloat16(a), hb = __float2bfloat16(b);
    h = __nv_bfloat162(ha, hb);
    l = __nv_bfloat162(__float2bfloat16(a - __bfloat162float(ha)),
                       __float2bfloat16(b - __bfloat162float(hb)));
}

// ---------------------------------------------------------------------------
// Prep kernels
// ---------------------------------------------------------------------------
__global__ void conv_act(const float* __restrict__ in,
                         __nv_bfloat16* __restrict__ oh,
                         __nv_bfloat16* __restrict__ ol, int n) {
    int i = (blockIdx.x * blockDim.x + threadIdx.x) * 4;
    if (i >= n) return;
    float4 v = *(const float4*)(in + i);
    __nv_bfloat162 h0, l0, h1, l1;
    split2(v.x, v.y, h0, l0);
    split2(v.z, v.w, h1, l1);
    __nv_bfloat162* ph = (__nv_bfloat162*)(oh + i);
    __nv_bfloat162* pl = (__nv_bfloat162*)(ol + i);
    ph[0] = h0; ph[1] = h1;
    pl[0] = l0; pl[1] = l1;
}

// All four W [Kdim, Ndim] fp32 -> WT [Ndim, Kdim] hi/lo bf16, one launch.
__global__ void conv_w_all(const float* __restrict__ Wq, const float* __restrict__ Wk,
                           const float* __restrict__ Wv, const float* __restrict__ Wo,
                           __nv_bfloat16* __restrict__ qh, __nv_bfloat16* __restrict__ ql,
                           __nv_bfloat16* __restrict__ kh, __nv_bfloat16* __restrict__ kl,
                           __nv_bfloat16* __restrict__ vh, __nv_bfloat16* __restrict__ vl,
                           __nv_bfloat16* __restrict__ oh, __nv_bfloat16* __restrict__ ol) {
    __shared__ float t[32][33];
    int bid = blockIdx.x;
    const float* in; __nv_bfloat16 *doh, *dol; int Ndim, nx, sid;
    if (bid < 4096)      { in = Wq; doh = qh; dol = ql; Ndim = D_MODEL; nx = 64; sid = bid; }
    else if (bid < 5120) { in = Wk; doh = kh; dol = kl; Ndim = KV_D;   nx = 16; sid = bid - 4096; }
    else if (bid < 6144) { in = Wv; doh = vh; dol = vl; Ndim = KV_D;   nx = 16; sid = bid - 5120; }
    else                 { in = Wo; doh = oh; dol = ol; Ndim = D_MODEL; nx = 64; sid = bid - 6144; }
    int n0 = (sid % nx) * 32, k0 = (sid / nx) * 32;
    int tx = threadIdx.x, ty = threadIdx.y;
#pragma unroll
    for (int i = 0; i < 4; ++i)
        t[ty + 8 * i][tx] = in[(size_t)(k0 + ty + 8 * i) * Ndim + n0 + tx];
    __syncthreads();
#pragma unroll
    for (int i = 0; i < 4; ++i) {
        int nl = ty + 8 * i;
        float v = t[tx][nl];
        __nv_bfloat16 h = __float2bfloat16(v);
        size_t o = (size_t)(n0 + nl) * D_MODEL + k0 + tx;   // Kdim == D_MODEL always
        doh[o] = h;
        dol[o] = __float2bfloat16(v - __bfloat162float(h));
    }
}

// cos/sin table: angle(t, i) = t * theta^{-i/64}, fp64 reduce, fp32 store
__global__ void rope_table(float2* __restrict__ tab) {
    int idx = blockIdx.x * blockDim.x + threadIdx.x;
    if (idx >= N_TOK * 64) return;
    int t = idx >> 6, i = idx & 63;
    double inv = exp(-9.210340371976184 * ((double)i / 64.0));
    double ang = (double)t * inv;
    double k = floor(ang * 0.15915494309189535);
    float r = (float)(ang - k * 6.283185307179586);
    float s, c;
    sincosf(r, &s, &c);
    tab[idx] = make_float2(c, s);
}

// ---------------------------------------------------------------------------
// Shared GEMM core: bf16x3-split mainloop, acc stays in registers.
// A [*,K] hi/lo row-major (pre-offset to block), Bt [*,K] hi/lo (pre-offset).
// ---------------------------------------------------------------------------
template <int BN>
__device__ __forceinline__ void gemm_core(
    const __nv_bfloat16* __restrict__ pAh, const __nv_bfloat16* __restrict__ pAl,
    const __nv_bfloat16* __restrict__ pBh, const __nv_bfloat16* __restrict__ pBl,
    int K, char* smem, uint32_t sbase, float acc[2][BN / 16][4]) {
    constexpr int BM = 128;
    constexpr int WN = BN / 2;
    constexpr int NBF = WN / 16;
    constexpr int NJ = BN / 16;
    constexpr int RS = 80;
    constexpr int OAl = BM * RS;
    constexpr int OBh = 2 * BM * RS;
    constexpr int OBl = 2 * BM * RS + BN * RS;
    constexpr int SBUF = 2 * BM * RS + 2 * BN * RS;
    constexpr int NBCH = BN * 4 / 256;

    const int tid = threadIdx.x;
    const int lane = tid & 31;
    const int wid = tid >> 5;
    const int warp_m = wid & 3;
    const int warp_n = wid >> 2;

    const int q = lane >> 3;
    const int rowA = (lane & 7) + (q & 1) * 8;
    const int colA = (q >> 1) * 16;
    const int rowB = (lane & 7) + (q >> 1) * 8;
    const int colB = (q & 1) * 16;

    const int NC = K / 32;
    {
        char* db = smem;
#pragma unroll
        for (int i = 0; i < 2; ++i) {
            int idx = tid + i * 256;
            int r = idx >> 2, c = idx & 3;
            *(uint4*)(db + r * RS + c * 16) =
                *(const uint4*)((const char*)pAh + ((size_t)r * K) * 2 + c * 16);
            *(uint4*)(db + OAl + r * RS + c * 16) =
                *(const uint4*)((const char*)pAl + ((size_t)r * K) * 2 + c * 16);
        }
#pragma unroll
        for (int i = 0; i < NBCH; ++i) {
            int idx = tid + i * 256;
            int r = idx >> 2, c = idx & 3;
            *(uint4*)(db + OBh + r * RS + c * 16) =
                *(const uint4*)((const char*)pBh + ((size_t)r * K) * 2 + c * 16);
            *(uint4*)(db + OBl + r * RS + c * 16) =
                *(const uint4*)((const char*)pBl + ((size_t)r * K) * 2 + c * 16);
        }
    }
    __syncthreads();

    for (int cch = 0; cch < NC; ++cch) {
        const int b = cch & 1;
        const uint32_t sb = sbase + b * SBUF;

        uint4 fAh[2], fAl[2], fBh[NBCH], fBl[NBCH];
        if (cch + 1 < NC) {
            const size_t k0b = (size_t)(cch + 1) * 32 * 2;
#pragma unroll
            for (int i = 0; i < 2; ++i) {
                int idx = tid + i * 256;
                int r = idx >> 2, c = idx & 3;
                fAh[i] = *(const uint4*)((const char*)pAh + (size_t)r * K * 2 + k0b + c * 16);
                fAl[i] = *(const uint4*)((const char*)pAl + (size_t)r * K * 2 + k0b + c * 16);
            }
#pragma unroll
            for (int i = 0; i < NBCH; ++i) {
                int idx = tid + i * 256;
                int r = idx >> 2, c = idx & 3;
                fBh[i] = *(const uint4*)((const char*)pBh + (size_t)r * K * 2 + k0b + c * 16);
                fBl[i] = *(const uint4*)((const char*)pBl + (size_t)r * K * 2 + k0b + c * 16);
            }
        }

#pragma unroll
        for (int ks = 0; ks < 2; ++ks) {
            uint32_t ah[2][4], al[2][4], bh[NBF][4], bl[NBF][4];
#pragma unroll
            for (int im = 0; im < 2; ++im) {
                uint32_t ra = sb + (warp_m * 32 + im * 16 + rowA) * RS + ks * 32 + colA;
                LDSM4(ah[im], ra);
                LDSM4(al[im], ra + OAl);
            }
#pragma unroll
            for (int ib = 0; ib < NBF; ++ib) {
                uint32_t rb = sb + OBh + (warp_n * WN + ib * 16 + rowB) * RS + ks * 32 + colB;
                LDSM4(bh[ib], rb);
                LDSM4(bl[ib], rb + (OBl - OBh));
            }
#pragma unroll
            for (int im = 0; im < 2; ++im)
#pragma unroll
                for (int j = 0; j < NJ; ++j) {
                    const int f = j >> 1, h = (j & 1) * 2;
                    MMA16816(acc[im][j], ah[im], bh[f][h], bh[f][h + 1]);
                    MMA16816(acc[im][j], ah[im], bl[f][h], bl[f][h + 1]);
                    MMA16816(acc[im][j], al[im], bh[f][h], bh[f][h + 1]);
                }
        }

        if (cch + 1 < NC) {
            char* db = smem + (b ^ 1) * SBUF;
#pragma unroll
            for (int i = 0; i < 2; ++i) {
                int idx = tid + i * 256;
                int r = idx >> 2, c = idx & 3;
                *(uint4*)(db + r * RS + c * 16) = fAh[i];
                *(uint4*)(db + OAl + r * RS + c * 16) = fAl[i];
            }
#pragma unroll
            for (int i = 0; i < NBCH; ++i) {
                int idx = tid + i * 256;
                int r = idx >> 2, c = idx & 3;
                *(uint4*)(db + OBh + r * RS + c * 16) = fBh[i];
                *(uint4*)(db + OBl + r * RS + c * 16) = fBl[i];
            }
            __syncthreads();
        }
    }
}

// Rope+split epilogue helper: thread fragment cols are (col, col+1) rope pairs.
__device__ __forceinline__ void rope_split_store(
    const float2* __restrict__ tab, float v0, float v1, int row, int col, int N,
    __nv_bfloat16* __restrict__ oh, __nv_bfloat16* __restrict__ ol) {
    float2 cs = tab[row * 64 + ((col & 127) >> 1)];
    float oe = v0 * cs.x - v1 * cs.y;
    float oo = v0 * cs.y + v1 * cs.x;
    __nv_bfloat162 h, l;
    split2(oe, oo, h, l);
    *(__nv_bfloat162*)(oh + (size_t)row * N + col) = h;
    *(__nv_bfloat162*)(ol + (size_t)row * N + col) = l;
}

// ---- Q projection: BN=128, rope+split epilogue -> qh/ql -------------------
__global__ void __launch_bounds__(256) hgemm_q(
    const __nv_bfloat16* __restrict__ Ah, const __nv_bfloat16* __restrict__ Al,
    const __nv_bfloat16* __restrict__ Bh, const __nv_bfloat16* __restrict__ Bl,
    __nv_bfloat16* __restrict__ oh, __nv_bfloat16* __restrict__ ol,
    const float2* __restrict__ tab) {
    extern __shared__ char smem[];
    const uint32_t sbase = smem_u32(smem);
    const int m0 = blockIdx.y * 128, n0 = blockIdx.x * 128;
    const int K = D_MODEL, N = D_MODEL;
    float acc[2][8][4];
#pragma unroll
    for (int im = 0; im < 2; ++im)
#pragma unroll
        for (int j = 0; j < 8; ++j)
#pragma unroll
            for (int e = 0; e < 4; ++e) acc[im][j][e] = 0.f;
    gemm_core<128>(Ah + (size_t)m0 * K, Al + (size_t)m0 * K,
                   Bh + (size_t)n0 * K, Bl + (size_t)n0 * K, K, smem, sbase, acc);
    const int lane = threadIdx.x & 31, wid = threadIdx.x >> 5;
#pragma unroll
    for (int im = 0; im < 2; ++im)
#pragma unroll
        for (int j = 0; j < 8; ++j) {
            int row = m0 + (wid & 3) * 32 + im * 16 + (lane >> 2);
            int col = n0 + (wid >> 2) * 64 + j * 8 + (lane & 3) * 2;
            rope_split_store(tab, acc[im][j][0], acc[im][j][1], row, col, N, oh, ol);
            rope_split_store(tab, acc[im][j][2], acc[im][j][3], row + 8, col, N, oh, ol);
        }
}

// ---- K+V projections batched: BN=64. K -> rope+split; V -> transpose+split.
__global__ void __launch_bounds__(256) hgemm_kv(
    const __nv_bfloat16* __restrict__ Ah, const __nv_bfloat16* __restrict__ Al,
    const __nv_bfloat16* __restrict__ KBh, const __nv_bfloat16* __restrict__ KBl,
    const __nv_bfloat16* __restrict__ VBh, const __nv_bfloat16* __restrict__ VBl,
    __nv_bfloat16* __restrict__ kh, __nv_bfloat16* __restrict__ kl,
    __nv_bfloat16* __restrict__ vth, __nv_bfloat16* __restrict__ vtl,
    const float2* __restrict__ tab) {
    extern __shared__ char smem[];
    const uint32_t sbase = smem_u32(smem);
    const bool isV = blockIdx.x >= 128;
    const int sid = blockIdx.x & 127;
    const int m0 = (sid >> 3) * 128, n0 = (sid & 7) * 64;
    const int K = D_MODEL;
    const __nv_bfloat16* Bh = isV ? VBh : KBh;
    const __nv_bfloat16* Bl = isV ? VBl : KBl;
    float acc[2][4][4];
#pragma unroll
    for (int im = 0; im < 2; ++im)
#pragma unroll
        for (int j = 0; j < 4; ++j)
#pragma unroll
            for (int e = 0; e < 4; ++e) acc[im][j][e] = 0.f;
    gemm_core<64>(Ah + (size_t)m0 * K, Al + (size_t)m0 * K,
                  Bh + (size_t)n0 * K, Bl + (size_t)n0 * K, K, smem, sbase, acc);
    const int tid = threadIdx.x;
    const int lane = tid & 31, wid = tid >> 5;
    if (!isV) {
#pragma unroll
        for (int im = 0; im < 2; ++im)
#pragma unroll
            for (int j = 0; j < 4; ++j) {
                int row = m0 + (wid & 3) * 32 + im * 16 + (lane >> 2);
                int col = n0 + (wid >> 2) * 32 + j * 8 + (lane & 3) * 2;
                rope_split_store(tab, acc[im][j][0], acc[im][j][1], row, col, KV_D, kh, kl);
                rope_split_store(tab, acc[im][j][2], acc[im][j][3], row + 8, col, KV_D, kh, kl);
            }
    } else {
        // stage fp32 tile transposed in smem, then split+store [kv][d][n]
        __syncthreads();
        float* tS = (float*)smem;   // [64][130]
#pragma unroll
        for (int im = 0; im < 2; ++im)
#pragma unroll
            for (int j = 0; j < 4; ++j) {
                int r = (wid & 3) * 32 + im * 16 + (lane >> 2);
                int cl = (wid >> 2) * 32 + j * 8 + (lane & 3) * 2;
                tS[cl * 130 + r] = acc[im][j][0];
                tS[(cl + 1) * 130 + r] = acc[im][j][1];
                tS[cl * 130 + r + 8] = acc[im][j][2];
                tS[(cl + 1) * 130 + r + 8] = acc[im][j][3];
            }
        __syncthreads();
        const int dkv = n0 >> 7, d_base = n0 & 127;
        const int rowl = tid >> 2, s32 = (tid & 3) * 32;
        size_t dst = (size_t)dkv * 128 * N_TOK + (size_t)(d_base + rowl) * N_TOK + m0 + s32;
#pragma unroll
        for (int k = 0; k < 32; k += 2) {
            __nv_bfloat162 h, l;
            split2(tS[rowl * 130 + s32 + k], tS[rowl * 130 + s32 + k + 1], h, l);
            *(__nv_bfloat162*)(vth + dst + k) = h;
            *(__nv_bfloat162*)(vtl + dst + k) = l;
        }
    }
}

// ---- Output projection: BN=128, fp32 C epilogue ---------------------------
__global__ void __launch_bounds__(256) hgemm_o(
    const __nv_bfloat16* __restrict__ Ah, const __nv_bfloat16* __restrict__ Al,
    const __nv_bfloat16* __restrict__ Bh, const __nv_bfloat16* __restrict__ Bl,
    float* __restrict__ C) {
    extern __shared__ char smem[];
    const uint32_t sbase = smem_u32(smem);
    const int m0 = blockIdx.y * 128, n0 = blockIdx.x * 128;
    const int K = D_MODEL, N = D_MODEL;
    float acc[2][8][4];
#pragma unroll
    for (int im = 0; im < 2; ++im)
#pragma unroll
        for (int j = 0; j < 8; ++j)
#pragma unroll
            for (int e = 0; e < 4; ++e) acc[im][j][e] = 0.f;
    gemm_core<128>(Ah + (size_t)m0 * K, Al + (size_t)m0 * K,
                   Bh + (size_t)n0 * K, Bl + (size_t)n0 * K, K, smem, sbase, acc);
    const int lane = threadIdx.x & 31, wid = threadIdx.x >> 5;
#pragma unroll
    for (int im = 0; im < 2; ++im)
#pragma unroll
        for (int j = 0; j < 8; ++j) {
            int row = m0 + (wid & 3) * 32 + im * 16 + (lane >> 2);
            int col = n0 + (wid >> 2) * 64 + j * 8 + (lane & 3) * 2;
            *(float2*)(C + (size_t)row * N + col) = make_float2(acc[im][j][0], acc[im][j][1]);
            *(float2*)(C + (size_t)(row + 8) * N + col) = make_float2(acc[im][j][2], acc[im][j][3]);
        }
}

// ---------------------------------------------------------------------------
// Tensor-core flash attention (unchanged from R4, cleaned).
// ---------------------------------------------------------------------------
#define RSQ 272
#define RSV 144
#define OQH 0
#define OQL (OQH + 128 * RSQ)
#define OKH (OQL + 128 * RSQ)
#define OKL (OKH + 64 * RSQ)
#define OVH (OKL + 64 * RSQ)
#define OVL (OVH + 128 * RSV)
#define OPH (OVL + 128 * RSV)
#define OPL (OPH + 128 * RSV)
#define FSMEM (OPL + 128 * RSV)

__global__ void __launch_bounds__(256, 1) flash_mma(
    const __nv_bfloat16* __restrict__ Qh, const __nv_bfloat16* __restrict__ Ql,
    const __nv_bfloat16* __restrict__ Kh, const __nv_bfloat16* __restrict__ Kl,
    const __nv_bfloat16* __restrict__ Vth, const __nv_bfloat16* __restrict__ Vtl,
    __nv_bfloat16* __restrict__ ch, __nv_bfloat16* __restrict__ cl) {
    const int qt = gridDim.x - 1 - blockIdx.x;
    const int h  = blockIdx.y;
    const int g  = h >> 2, kv = h & 3;
    const int qcol0 = g * 512 + kv * 128;
    const int kcol0 = kv * 128;
    const int ocol0 = (kv * 4 + g) * 128;
    const __nv_bfloat16* vh = Vth + (size_t)kv * 128 * N_TOK;
    const __nv_bfloat16* vl = Vtl + (size_t)kv * 128 * N_TOK;

    extern __shared__ char smem[];
    const uint32_t sbase = smem_u32(smem);

    const int tid = threadIdx.x;
    const int lane = tid & 31;
    const int warp_m = tid >> 5;
    const int q4 = lane >> 2, l4 = lane & 3;
    const int qq = lane >> 3;
    const int rowA = (lane & 7) + (qq & 1) * 8;
    const int colA = (qq >> 1) * 16;
    const int rowB = (lane & 7) + (qq >> 1) * 8;
    const int colB = (qq & 1) * 16;
    const float SCALE = 0.08838834764831845f;

#pragma unroll
    for (int i = 0; i < 8; ++i) {
        int idx = tid + i * 256;
        int r = idx >> 4, c = idx & 15;
        size_t go = (size_t)(qt * 128 + r) * D_MODEL + qcol0 + c * 8;
        *(uint4*)(smem + OQH + r * RSQ + c * 16) = *(const uint4*)(Qh + go);
        *(uint4*)(smem + OQL + r * RSQ + c * 16) = *(const uint4*)(Ql + go);
    }

    float o[16][4];
#pragma unroll
    for (int f = 0; f < 16; ++f)
#pragma unroll
        for (int e = 0; e < 4; ++e) o[f][e] = 0.f;
    float m0 = -1e30f, m1 = -1e30f, l0 = 0.f, l1 = 0.f;

    const int nkt = 2 * qt + 2;
    for (int kt = 0; kt < nkt; ++kt) {
        __syncthreads();
#pragma unroll
        for (int i = 0; i < 4; ++i) {
            int idx = tid + i * 256;
            int r = idx >> 4, c = idx & 15;
            size_t go = (size_t)(kt * 64 + r) * KV_D + kcol0 + c * 8;
            *(uint4*)(smem + OKH + r * RSQ + c * 16) = *(const uint4*)(Kh + go);
            *(uint4*)(smem + OKL + r * RSQ + c * 16) = *(const uint4*)(Kl + go);
        }
#pragma unroll
        for (int i = 0; i < 4; ++i) {
            int idx = tid + i * 256;
            int r = idx >> 3, c = idx & 7;
            size_t go = (size_t)r * N_TOK + kt * 64 + c * 8;
            *(uint4*)(smem + OVH + r * RSV + c * 16) = *(const uint4*)(vh + go);
            *(uint4*)(smem + OVL + r * RSV + c * 16) = *(const uint4*)(vl + go);
        }
        __syncthreads();

        const int rbase = qt * 128 + warp_m * 16;
        const bool active = (kt * 64) <= (rbase + 15);

        if (active) {
            float sacc[8][4];
#pragma unroll
            for (int j = 0; j < 8; ++j)
#pragma unroll
                for (int e = 0; e < 4; ++e) sacc[j][e] = 0.f;
#pragma unroll
            for (int ks = 0; ks < 8; ++ks) {
                uint32_t ah[4], al[4], bh[4], bl[4];
                uint32_t ra = sbase + OQH + (warp_m * 16 + rowA) * RSQ + ks * 32 + colA;
                LDSM4(ah, ra);
                LDSM4(al, ra + (OQL - OQH));
#pragma unroll
                for (int ib = 0; ib < 4; ++ib) {
                    uint32_t rb = sbase + OKH + (ib * 16 + rowB) * RSQ + ks * 32 + colB;
                    LDSM4(bh, rb);
                    LDSM4(bl, rb + (OKL - OKH));
#pragma unroll
                    for (int half = 0; half < 2; ++half) {
                        MMA16816(sacc[ib * 2 + half], ah, bh[half * 2], bh[half * 2 + 1]);
                        MMA16816(sacc[ib * 2 + half], ah, bl[half * 2], bl[half * 2 + 1]);
                        MMA16816(sacc[ib * 2 + half], al, bh[half * 2], bh[half * 2 + 1]);
                    }
                }
            }
            const bool needMask = (kt * 64 + 63) > rbase;
#pragma unroll
            for (int j = 0; j < 8; ++j)
#pragma unroll
                for (int e = 0; e < 4; ++e) {
                    float v = sacc[j][e] * SCALE;
                    if (needMask) {
                        int rg = rbase + q4 + (e >> 1) * 8;
                        int kg = kt * 64 + j * 8 + l4 * 2 + (e & 1);
                        if (kg > rg) v = -1e30f;
                    }
                    sacc[j][e] = v;
                }
            float mx0 = -1e30f, mx1 = -1e30f;
#pragma unroll
            for (int j = 0; j < 8; ++j) {
                mx0 = fmaxf(mx0, fmaxf(sacc[j][0], sacc[j][1]));
                mx1 = fmaxf(mx1, fmaxf(sacc[j][2], sacc[j][3]));
            }
            mx0 = fmaxf(mx0, __shfl_xor_sync(0xffffffffu, mx0, 1));
            mx0 = fmaxf(mx0, __shfl_xor_sync(0xffffffffu, mx0, 2));
            mx1 = fmaxf(mx1, __shfl_xor_sync(0xffffffffu, mx1, 1));
            mx1 = fmaxf(mx1, __shfl_xor_sync(0xffffffffu, mx1, 2));
            float nm0 = fmaxf(m0, mx0), nm1 = fmaxf(m1, mx1);
            float corr0 = fexp(m0 - nm0), corr1 = fexp(m1 - nm1);
            m0 = nm0; m1 = nm1;
            float s0 = 0.f, s1 = 0.f;
            uint32_t prow0 = sbase + OPH + (warp_m * 16 + q4) * RSV + l4 * 4;
            uint32_t prow1 = prow0 + 8 * RSV;
#pragma unroll
            for (int j = 0; j < 8; ++j) {
                float p00 = fexp(sacc[j][0] - m0);
                float p01 = fexp(sacc[j][1] - m0);
                float p10 = fexp(sacc[j][2] - m1);
                float p11 = fexp(sacc[j][3] - m1);
                s0 += p00 + p01; s1 += p10 + p11;
                __nv_bfloat162 hp0, lp0, hp1, lp1;
                split2(p00, p01, hp0, lp0);
                split2(p10, p11, hp1, lp1);
                asm volatile("st.shared.b32 [%0], %1;" :: "r"(prow0 + j * 16), "r"(*(uint32_t*)&hp0));
                asm volatile("st.shared.b32 [%0], %1;" :: "r"(prow1 + j * 16), "r"(*(uint32_t*)&hp1));
                asm volatile("st.shared.b32 [%0], %1;" :: "r"(prow0 + (OPL - OPH) + j * 16), "r"(*(uint32_t*)&lp0));
                asm volatile("st.shared.b32 [%0], %1;" :: "r"(prow1 + (OPL - OPH) + j * 16), "r"(*(uint32_t*)&lp1));
            }
            s0 += __shfl_xor_sync(0xffffffffu, s0, 1);
            s0 += __shfl_xor_sync(0xffffffffu, s0, 2);
            s1 += __shfl_xor_sync(0xffffffffu, s1, 1);
            s1 += __shfl_xor_sync(0xffffffffu, s1, 2);
            l0 = l0 * corr0 + s0;
            l1 = l1 * corr1 + s1;
#pragma unroll
            for (int f = 0; f < 16; ++f) {
                o[f][0] *= corr0; o[f][1] *= corr0;
                o[f][2] *= corr1; o[f][3] *= corr1;
            }
        }
        __syncthreads();

        if (active) {
#pragma unroll
            for (int ks = 0; ks < 4; ++ks) {
                uint32_t pa[4], pl_[4];
                uint32_t raddr = sbase + OPH + (warp_m * 16 + rowA) * RSV + ks * 32 + colA;
                LDSM4(pa, raddr);
                LDSM4(pl_, raddr + (OPL - OPH));
#pragma unroll
                for (int ib = 0; ib < 8; ++ib) {
                    uint32_t vb[4], vbl[4];
                    uint32_t b0 = sbase + OVH + (ib * 16 + rowB) * RSV + ks * 32 + colB;
                    LDSM4(vb, b0);
                    LDSM4(vbl, b0 + (OVL - OVH));
#pragma unroll
                    for (int half = 0; half < 2; ++half) {
                        MMA16816(o[ib * 2 + half], pa, vb[half * 2], vb[half * 2 + 1]);
                        MMA16816(o[ib * 2 + half], pa, vbl[half * 2], vbl[half * 2 + 1]);
                        MMA16816(o[ib * 2 + half], pl_, vb[half * 2], vb[half * 2 + 1]);
                    }
                }
            }
        }
    }

    float i0 = 1.f / l0, i1 = 1.f / l1;
    int row0 = qt * 128 + warp_m * 16 + q4;
#pragma unroll
    for (int f = 0; f < 16; ++f) {
        int col = ocol0 + f * 8 + l4 * 2;
        __nv_bfloat162 h0, l0v, h1, l1v;
        split2(o[f][0] * i0, o[f][1] * i0, h0, l0v);
        split2(o[f][2] * i1, o[f][3] * i1, h1, l1v);
        *(__nv_bfloat162*)(ch + (size_t)row0 * D_MODEL + col) = h0;
        *(__nv_bfloat162*)(ch + (size_t)(row0 + 8) * D_MODEL + col) = h1;
        *(__nv_bfloat162*)(cl + (size_t)row0 * D_MODEL + col) = l0v;
        *(__nv_bfloat162*)(cl + (size_t)(row0 + 8) * D_MODEL + col) = l1v;
    }
}

// ---------------------------------------------------------------------------
extern "C" void kernel_launch(void* const* d_in, const int* in_sizes, int n_in,
                              void* d_out, int out_size) {
    const float* x  = (const float*)d_in[0];
    const float* Wq = (const float*)d_in[1];
    const float* Wk = (const float*)d_in[2];
    const float* Wv = (const float*)d_in[3];
    const float* Wo = (const float*)d_in[4];
    float* out = (float*)d_out;

    __nv_bfloat16 *xh, *xl, *ch, *cl, *qh, *ql, *kh, *kl, *vth, *vtl;
    __nv_bfloat16 *qth, *qtl, *kth, *ktl, *vwh, *vwl, *oth, *otl;
    float2* tab;
    cudaGetSymbolAddress((void**)&xh, g_xh);   cudaGetSymbolAddress((void**)&xl, g_xl);
    cudaGetSymbolAddress((void**)&ch, g_ch);   cudaGetSymbolAddress((void**)&cl, g_cl);
    cudaGetSymbolAddress((void**)&qh, g_Qh);   cudaGetSymbolAddress((void**)&ql, g_Ql);
    cudaGetSymbolAddress((void**)&kh, g_Kh);   cudaGetSymbolAddress((void**)&kl, g_Kl);
    cudaGetSymbolAddress((void**)&vth, g_Vth); cudaGetSymbolAddress((void**)&vtl, g_Vtl);
    cudaGetSymbolAddress((void**)&qth, g_WqTh); cudaGetSymbolAddress((void**)&qtl, g_WqTl);
    cudaGetSymbolAddress((void**)&kth, g_WkTh); cudaGetSymbolAddress((void**)&ktl, g_WkTl);
    cudaGetSymbolAddress((void**)&vwh, g_WvTh); cudaGetSymbolAddress((void**)&vwl, g_WvTl);
    cudaGetSymbolAddress((void**)&oth, g_WoTh); cudaGetSymbolAddress((void**)&otl, g_WoTl);
    cudaGetSymbolAddress((void**)&tab, g_rope);

    const int smem128 = 2 * (2 * 128 * 80 + 2 * 128 * 80);  // 81920
    const int smem64  = 2 * (2 * 128 * 80 + 2 * 64 * 80);   // 61440
    cudaFuncSetAttribute(hgemm_q,  cudaFuncAttributeMaxDynamicSharedMemorySize, smem128);
    cudaFuncSetAttribute(hgemm_o,  cudaFuncAttributeMaxDynamicSharedMemorySize, smem128);
    cudaFuncSetAttribute(hgemm_kv, cudaFuncAttributeMaxDynamicSharedMemorySize, smem64);
    cudaFuncSetAttribute(flash_mma, cudaFuncAttributeMaxDynamicSharedMemorySize, FSMEM);

    // 0: split x
    conv_act<<<(N_TOK * D_MODEL / 4 + 255) / 256, 256>>>(x, xh, xl, N_TOK * D_MODEL);
    // 1: split+transpose all weights
    conv_w_all<<<10240, dim3(32, 8)>>>(Wq, Wk, Wv, Wo, qth, qtl, kth, ktl,
                                       vwh, vwl, oth, otl);
    // 2: rope table
    rope_table<<<(N_TOK * 64 + 255) / 256, 256>>>(tab);
    // 3: Q projection (+rope+split fused)
    hgemm_q<<<dim3(16, 16), 256, smem128>>>(xh, xl, qth, qtl, qh, ql, tab);
    // 4: K+V projections batched (+rope / +transpose fused)
    hgemm_kv<<<256, 256, smem64>>>(xh, xl, kth, ktl, vwh, vwl, kh, kl, vth, vtl, tab);
    // 5: attention (profiled by ncu -s 5)
    flash_mma<<<dim3(N_TOK / 128, 16), 256, FSMEM>>>(qh, ql, kh, kl, vth, vtl, ch, cl);
    // 6: output projection
    hgemm_o<<<dim3(16, 16), 256, smem128>>>(ch, cl, oth, otl, out);

    (void)in_sizes; (void)n_in; (void)out_size;
}